// round 1
// baseline (speedup 1.0000x reference)
#include <cuda_runtime.h>
#include <math.h>

// ---------------- problem constants ----------------
#define T_STEPS 64
#define B_SZ    128
#define M_COLS  1000
#define N_CELLS 4
#define TC      4000      // M_COLS * N_CELLS
#define K_TOP   25
#define D_IN    1024
#define D_OUT   1024

// ---------------- persistent device state ----------------
__device__ float g_psi [B_SZ * TC];   // memory trace (== x_b carry)
__device__ float g_phi [B_SZ * TC];   // inhibition trace
__device__ float g_za  [B_SZ * M_COLS];
__device__ float g_zb  [B_SZ * TC];
__device__ float g_ycol[B_SZ * M_COLS];

// ---------------- init ----------------
__global__ void zero_state_kernel() {
    int i = blockIdx.x * blockDim.x + threadIdx.x;
    int n = B_SZ * TC;
    if (i < n) { g_psi[i] = 0.f; g_phi[i] = 0.f; }
}

// ---------------- NT SGEMM: C[m,n] = sum_k A[m,k]*B[n,k] (+bias[n]) ----------------
// A: Mrows x Kdim row-major, B: Ncols x Kdim row-major, C: Mrows x Ncols row-major.
// Kdim must be divisible by BK.
template<int BM, int BN, int BK, int TM, int TN>
__global__ void sgemm_nt(int Mrows, int Ncols, int Kdim,
                         const float* __restrict__ A,
                         const float* __restrict__ B,
                         float* __restrict__ C,
                         const float* __restrict__ bias)
{
    constexpr int THREADS = (BM / TM) * (BN / TN);
    __shared__ float As[BK][BM + 4];
    __shared__ float Bs[BK][BN + 4];

    const int tid = threadIdx.x;
    const int tn  = tid % (BN / TN);
    const int tm  = tid / (BN / TN);
    const int m0  = blockIdx.y * BM;
    const int n0  = blockIdx.x * BN;

    float acc[TM][TN];
#pragma unroll
    for (int i = 0; i < TM; i++)
#pragma unroll
        for (int j = 0; j < TN; j++) acc[i][j] = 0.f;

    for (int k0 = 0; k0 < Kdim; k0 += BK) {
        // load A tile (BM x BK) -> As[k][m]
#pragma unroll 2
        for (int i = tid; i < BM * BK; i += THREADS) {
            int m = i / BK, k = i % BK;
            int gm = m0 + m;
            float v = 0.f;
            if (gm < Mrows) v = A[(size_t)gm * Kdim + k0 + k];
            As[k][m] = v;
        }
        // load B tile (BN x BK) -> Bs[k][n]
#pragma unroll 2
        for (int i = tid; i < BN * BK; i += THREADS) {
            int n = i / BK, k = i % BK;
            int gn = n0 + n;
            float v = 0.f;
            if (gn < Ncols) v = B[(size_t)gn * Kdim + k0 + k];
            Bs[k][n] = v;
        }
        __syncthreads();

#pragma unroll
        for (int k = 0; k < BK; k++) {
            float a[TM], bb[TN];
#pragma unroll
            for (int i = 0; i < TM; i++) a[i] = As[k][tm * TM + i];
#pragma unroll
            for (int j = 0; j < TN; j++) bb[j] = Bs[k][tn * TN + j];
#pragma unroll
            for (int i = 0; i < TM; i++)
#pragma unroll
                for (int j = 0; j < TN; j++) acc[i][j] = fmaf(a[i], bb[j], acc[i][j]);
        }
        __syncthreads();
    }

#pragma unroll
    for (int i = 0; i < TM; i++) {
        int gm = m0 + tm * TM + i;
        if (gm >= Mrows) continue;
#pragma unroll
        for (int j = 0; j < TN; j++) {
            int gn = n0 + tn * TN + j;
            if (gn >= Ncols) continue;
            float v = acc[i][j];
            if (bias) v += bias[gn];
            C[(size_t)gm * Ncols + gn] = v;
        }
    }
}

// ---------------- fused RSM step (inhibition, top-k, traces) ----------------
// one block per batch row
__global__ void rsm_step_kernel()
{
    const int b   = blockIdx.x;
    const int tid = threadIdx.x;
    const int NT  = blockDim.x;   // 256

    __shared__ float          s_lam[M_COLS];   // column max of pi
    __shared__ float          s_sig[M_COLS];   // sigma at winner cell
    __shared__ unsigned char  s_win[M_COLS];   // winner cell index
    __shared__ unsigned char  s_sel[M_COLS];   // selected column flag
    __shared__ float          s_rv[256];
    __shared__ int            s_ri[256];

    const float* zbb  = g_zb  + b * TC;
    const float* phib = g_phi + b * TC;
    const float* zab  = g_za  + b * M_COLS;

    // pass 1: per-column winner cell + column max of pi
    for (int c = tid; c < M_COLS; c += NT) {
        float zac  = zab[c];
        float best = -INFINITY;
        int   bw   = 0;
        float bsig = 0.f;
#pragma unroll
        for (int n = 0; n < N_CELLS; n++) {
            float sig = zac + zbb[c * N_CELLS + n];
            float p   = sig * (1.f - phib[c * N_CELLS + n]);
            if (p > best) { best = p; bw = n; bsig = sig; }   // strict > : first index wins ties
        }
        s_lam[c] = best;
        s_win[c] = (unsigned char)bw;
        s_sig[c] = bsig;
        s_sel[c] = 0;
    }
    __syncthreads();

    // pass 2: iterative top-K (value desc, index asc on ties) over 1000 columns
    for (int it = 0; it < K_TOP; it++) {
        float v  = -INFINITY;
        int   vi = M_COLS;
        for (int c = tid; c < M_COLS; c += NT) {
            float l = s_lam[c];
            if (l > v || (l == v && c < vi)) { v = l; vi = c; }
        }
        s_rv[tid] = v; s_ri[tid] = vi;
        __syncthreads();
        for (int s = NT / 2; s > 0; s >>= 1) {
            if (tid < s) {
                float ov = s_rv[tid + s]; int oi = s_ri[tid + s];
                if (ov > s_rv[tid] || (ov == s_rv[tid] && oi < s_ri[tid])) {
                    s_rv[tid] = ov; s_ri[tid] = oi;
                }
            }
            __syncthreads();
        }
        if (tid == 0) {
            int w = s_ri[0];
            s_sel[w] = 1;
            s_lam[w] = -INFINITY;
        }
        __syncthreads();
    }

    // pass 3: activation, y_col, trace updates
    float* psib = g_psi + b * TC;
    float* phiw = g_phi + b * TC;
    for (int c = tid; c < M_COLS; c += NT) {
        float y = 0.f;
        int   w = s_win[c];
        int   sel = s_sel[c];
        if (sel) y = tanhf(s_sig[c]);
        g_ycol[b * M_COLS + c] = fmaxf(y, 0.f);
#pragma unroll
        for (int n = 0; n < N_CELLS; n++) {
            float yc  = (sel && n == w) ? y : 0.f;
            int   idx = c * N_CELLS + n;
            psib[idx] = fmaxf(psib[idx] * 0.5f, yc);  // EPS   = 0.5
            phiw[idx] = fmaxf(phiw[idx] * 0.5f, yc);  // GAMMA = 0.5
        }
    }
}

// ---------------- host launch ----------------
extern "C" void kernel_launch(void* const* d_in, const int* in_sizes, int n_in,
                              void* d_out, int out_size)
{
    const float* x   = (const float*)d_in[0];   // [T, B, D_IN]
    const float* w_a = (const float*)d_in[1];   // [M, D_IN]
    const float* w_b = (const float*)d_in[2];   // [TC, TC]
    const float* w_d = (const float*)d_in[3];   // [D_OUT, M]
    const float* b_d = (const float*)d_in[4];   // [D_OUT]
    float* out = (float*)d_out;                 // [T, B, D_OUT]

    float *psi, *za, *zb, *ycol;
    cudaGetSymbolAddress((void**)&psi,  g_psi);
    cudaGetSymbolAddress((void**)&za,   g_za);
    cudaGetSymbolAddress((void**)&zb,   g_zb);
    cudaGetSymbolAddress((void**)&ycol, g_ycol);

    {
        int n = B_SZ * TC;
        zero_state_kernel<<<(n + 255) / 256, 256>>>();
    }

    // GEMM config: BM=64, BN=64, BK=8, TM=8, TN=4 -> 128 threads
    constexpr int BM = 64, BN = 64, BK = 8, TM = 8, TN = 4;
    constexpr int THREADS = (BM / TM) * (BN / TN);

    dim3 grid_za((M_COLS + BN - 1) / BN, (B_SZ + BM - 1) / BM);   // 16 x 2
    dim3 grid_zb((TC     + BN - 1) / BN, (B_SZ + BM - 1) / BM);   // 63 x 2
    dim3 grid_out((D_OUT + BN - 1) / BN, (B_SZ + BM - 1) / BM);   // 16 x 2

    for (int t = 0; t < T_STEPS; t++) {
        const float* xt = x + (size_t)t * B_SZ * D_IN;

        // z_a = x_t @ w_a^T   [128,1000]
        sgemm_nt<BM, BN, BK, TM, TN><<<grid_za, THREADS>>>(
            B_SZ, M_COLS, D_IN, xt, w_a, za, nullptr);

        // z_b = psi @ w_b^T   [128,4000]   (MEM_GAIN = 1)
        sgemm_nt<BM, BN, BK, TM, TN><<<grid_zb, THREADS>>>(
            B_SZ, TC, TC, psi, w_b, zb, nullptr);

        // fused inhibition / top-k / traces
        rsm_step_kernel<<<B_SZ, 256>>>();

        // out_t = y_col @ w_d^T + b_d   [128,1024]
        float* out_t = out + (size_t)t * B_SZ * D_OUT;
        sgemm_nt<BM, BN, BK, TM, TN><<<grid_out, THREADS>>>(
            B_SZ, D_OUT, M_COLS, ycol, w_d, out_t, b_d);
    }
}

// round 2
// speedup vs baseline: 6.7996x; 6.7996x over previous
#include <cuda_runtime.h>
#include <math.h>

// ---------------- problem constants ----------------
#define T_STEPS 64
#define B_SZ    128
#define M_COLS  1000
#define N_CELLS 4
#define TC      4000      // M_COLS * N_CELLS
#define K_TOP   25
#define D_IN    1024
#define D_OUT   1024
#define KSPLIT  5         // split-K factor for the z_b GEMM (4000/5 = 800)

// ---------------- persistent device state ----------------
__device__ float g_psi [B_SZ * TC];                 // memory trace (== x_b carry)
__device__ float g_phi [B_SZ * TC];                 // inhibition trace
__device__ float g_za_all [T_STEPS * B_SZ * M_COLS];// pre-computed feedforward drive
__device__ float g_zbp [KSPLIT * B_SZ * TC];        // split-K partials of z_b
__device__ float g_ycol_all[T_STEPS * B_SZ * M_COLS];// column activity for decode

// ---------------- init ----------------
__global__ void zero_state_kernel() {
    int i = blockIdx.x * blockDim.x + threadIdx.x;
    int n = B_SZ * TC;
    if (i < n) { g_psi[i] = 0.f; g_phi[i] = 0.f; }
}

// ---------------- NT SGEMM: C[m,n] = sum_k A[m,k]*B[n,k] (+bias[n]) ----------------
// A: Mrows x Kdim row-major, B: Ncols x Kdim row-major, C: Mrows x Ncols row-major.
// Split-K: blockIdx.z selects K-chunk [z*kChunk, (z+1)*kChunk), writes C + z*partStride.
// Requirements: Mrows % BM == 0, kChunk % BK == 0, Kdim % 4 == 0, BK % 4 == 0.
template<int BM, int BN, int BK, int TM, int TN>
__global__ void __launch_bounds__((BM/TM)*(BN/TN))
sgemm_nt_v2(int Mrows, int Ncols, int Kdim, int kChunk,
            const float* __restrict__ A,
            const float* __restrict__ B,
            float* __restrict__ C,
            const float* __restrict__ bias,
            size_t partStride)
{
    constexpr int THREADS = (BM / TM) * (BN / TN);
    __shared__ float As[BK][BM + 4];
    __shared__ float Bs[BK][BN + 4];

    const int tid  = threadIdx.x;
    const int tn   = tid % (BN / TN);
    const int tm   = tid / (BN / TN);
    const int m0   = blockIdx.y * BM;
    const int n0   = blockIdx.x * BN;
    const int kBase = blockIdx.z * kChunk;

    C += (size_t)blockIdx.z * partStride;

    float acc[TM][TN];
#pragma unroll
    for (int i = 0; i < TM; i++)
#pragma unroll
        for (int j = 0; j < TN; j++) acc[i][j] = 0.f;

    constexpr int AQ = BK / 4;               // float4 quads per A row
    constexpr int A_LOADS = BM * AQ;         // total float4 loads for A tile
    constexpr int B_LOADS = BN * AQ;

    for (int k0 = 0; k0 < kChunk; k0 += BK) {
        // load A tile (BM x BK) -> As[k][m], float4 along k
#pragma unroll
        for (int i = tid; i < A_LOADS; i += THREADS) {
            int row = i / AQ, q = i % AQ;
            int gm = m0 + row;
            float4 v = make_float4(0.f, 0.f, 0.f, 0.f);
            v = *reinterpret_cast<const float4*>(&A[(size_t)gm * Kdim + kBase + k0 + q * 4]);
            As[q * 4 + 0][row] = v.x;
            As[q * 4 + 1][row] = v.y;
            As[q * 4 + 2][row] = v.z;
            As[q * 4 + 3][row] = v.w;
        }
        // load B tile (BN x BK) -> Bs[k][n], float4 along k
#pragma unroll
        for (int i = tid; i < B_LOADS; i += THREADS) {
            int row = i / AQ, q = i % AQ;
            int gn = n0 + row;
            float4 v = make_float4(0.f, 0.f, 0.f, 0.f);
            if (gn < Ncols)
                v = *reinterpret_cast<const float4*>(&B[(size_t)gn * Kdim + kBase + k0 + q * 4]);
            Bs[q * 4 + 0][row] = v.x;
            Bs[q * 4 + 1][row] = v.y;
            Bs[q * 4 + 2][row] = v.z;
            Bs[q * 4 + 3][row] = v.w;
        }
        __syncthreads();

#pragma unroll
        for (int k = 0; k < BK; k++) {
            float4 a0 = *reinterpret_cast<const float4*>(&As[k][tm * TM]);
            float4 a1 = *reinterpret_cast<const float4*>(&As[k][tm * TM + 4]);
            float4 b0 = *reinterpret_cast<const float4*>(&Bs[k][tn * TN]);
            float a[TM] = {a0.x, a0.y, a0.z, a0.w, a1.x, a1.y, a1.z, a1.w};
            float bb[TN] = {b0.x, b0.y, b0.z, b0.w};
#pragma unroll
            for (int i = 0; i < TM; i++)
#pragma unroll
                for (int j = 0; j < TN; j++)
                    acc[i][j] = fmaf(a[i], bb[j], acc[i][j]);
        }
        __syncthreads();
    }

#pragma unroll
    for (int i = 0; i < TM; i++) {
        int gm = m0 + tm * TM + i;
#pragma unroll
        for (int j = 0; j < TN; j++) {
            int gn = n0 + tn * TN + j;
            if (gn >= Ncols) continue;
            float v = acc[i][j];
            if (bias) v += bias[gn];
            C[(size_t)gm * Ncols + gn] = v;
        }
    }
}

// ---------------- fused RSM step (split-K reduce, inhibition, top-k, traces) ----
// one block (256 threads) per batch row
__global__ void __launch_bounds__(256) rsm_step_kernel(int t)
{
    const int b      = blockIdx.x;
    const int tid    = threadIdx.x;
    const int lane   = tid & 31;
    const int warpid = tid >> 5;

    __shared__ float          s_lam[M_COLS];   // column max of pi
    __shared__ float          s_sig[M_COLS];   // sigma at winner cell
    __shared__ unsigned char  s_win[M_COLS];   // winner cell index
    __shared__ unsigned char  s_sel[M_COLS];   // selected column flag
    __shared__ float          s_rv[8];
    __shared__ int            s_ri[8];

    const float* zab  = g_za_all + ((size_t)t * B_SZ + b) * M_COLS;
    const float* phib = g_phi + b * TC;

    // pass 1: sum split-K partials, per-column winner cell + column max of pi
    for (int c = tid; c < M_COLS; c += 256) {
        float zac = zab[c];
        float4 zb = make_float4(0.f, 0.f, 0.f, 0.f);
#pragma unroll
        for (int p = 0; p < KSPLIT; p++) {
            float4 v = *reinterpret_cast<const float4*>(
                &g_zbp[(size_t)p * B_SZ * TC + b * TC + c * N_CELLS]);
            zb.x += v.x; zb.y += v.y; zb.z += v.z; zb.w += v.w;
        }
        float4 ph = *reinterpret_cast<const float4*>(&phib[c * N_CELLS]);
        float sig[4] = {zac + zb.x, zac + zb.y, zac + zb.z, zac + zb.w};
        float pv [4] = {sig[0] * (1.f - ph.x), sig[1] * (1.f - ph.y),
                        sig[2] * (1.f - ph.z), sig[3] * (1.f - ph.w)};
        float best = pv[0]; int bw = 0;
#pragma unroll
        for (int n = 1; n < N_CELLS; n++)
            if (pv[n] > best) { best = pv[n]; bw = n; }   // strict > : first index wins
        s_lam[c] = best;
        s_win[c] = (unsigned char)bw;
        s_sig[c] = sig[bw];
        s_sel[c] = 0;
    }
    __syncthreads();

    // pass 2: iterative top-K (value desc, index asc on ties) via warp shuffles
    for (int it = 0; it < K_TOP; it++) {
        float v  = -INFINITY;
        int   vi = 0x7fffffff;
        for (int c = tid; c < M_COLS; c += 256) {
            float l = s_lam[c];
            if (l > v || (l == v && c < vi)) { v = l; vi = c; }
        }
#pragma unroll
        for (int off = 16; off > 0; off >>= 1) {
            float ov = __shfl_down_sync(0xffffffffu, v, off);
            int   oi = __shfl_down_sync(0xffffffffu, vi, off);
            if (ov > v || (ov == v && oi < vi)) { v = ov; vi = oi; }
        }
        if (lane == 0) { s_rv[warpid] = v; s_ri[warpid] = vi; }
        __syncthreads();
        if (warpid == 0) {
            float v2  = (lane < 8) ? s_rv[lane] : -INFINITY;
            int   vi2 = (lane < 8) ? s_ri[lane] : 0x7fffffff;
#pragma unroll
            for (int off = 4; off > 0; off >>= 1) {
                float ov = __shfl_down_sync(0xffffffffu, v2, off);
                int   oi = __shfl_down_sync(0xffffffffu, vi2, off);
                if (ov > v2 || (ov == v2 && oi < vi2)) { v2 = ov; vi2 = oi; }
            }
            if (lane == 0) {
                s_sel[vi2] = 1;
                s_lam[vi2] = -INFINITY;
            }
        }
        __syncthreads();
    }

    // pass 3: activation, y_col, trace updates
    float* psib  = g_psi + b * TC;
    float* phiw  = g_phi + b * TC;
    float* ycolb = g_ycol_all + ((size_t)t * B_SZ + b) * M_COLS;
    for (int c = tid; c < M_COLS; c += 256) {
        float y   = 0.f;
        int   w   = s_win[c];
        int   sel = s_sel[c];
        if (sel) y = tanhf(s_sig[c]);
        ycolb[c] = fmaxf(y, 0.f);
        float4 ps = *reinterpret_cast<const float4*>(&psib[c * N_CELLS]);
        float4 ph = *reinterpret_cast<const float4*>(&phiw[c * N_CELLS]);
        float pso[4] = {ps.x, ps.y, ps.z, ps.w};
        float pho[4] = {ph.x, ph.y, ph.z, ph.w};
#pragma unroll
        for (int n = 0; n < N_CELLS; n++) {
            float yc = (sel && n == w) ? y : 0.f;
            pso[n] = fmaxf(pso[n] * 0.5f, yc);   // EPS   = 0.5
            pho[n] = fmaxf(pho[n] * 0.5f, yc);   // GAMMA = 0.5
        }
        *reinterpret_cast<float4*>(&psib[c * N_CELLS]) =
            make_float4(pso[0], pso[1], pso[2], pso[3]);
        *reinterpret_cast<float4*>(&phiw[c * N_CELLS]) =
            make_float4(pho[0], pho[1], pho[2], pho[3]);
    }
}

// ---------------- host launch ----------------
extern "C" void kernel_launch(void* const* d_in, const int* in_sizes, int n_in,
                              void* d_out, int out_size)
{
    const float* x   = (const float*)d_in[0];   // [T, B, D_IN]
    const float* w_a = (const float*)d_in[1];   // [M, D_IN]
    const float* w_b = (const float*)d_in[2];   // [TC, TC]
    const float* w_d = (const float*)d_in[3];   // [D_OUT, M]
    const float* b_d = (const float*)d_in[4];   // [D_OUT]
    float* out = (float*)d_out;                 // [T, B, D_OUT]

    float *psi, *za, *zbp, *ycol;
    cudaGetSymbolAddress((void**)&psi,  g_psi);
    cudaGetSymbolAddress((void**)&za,   g_za_all);
    cudaGetSymbolAddress((void**)&zbp,  g_zbp);
    cudaGetSymbolAddress((void**)&ycol, g_ycol_all);

    {
        int n = B_SZ * TC;
        zero_state_kernel<<<(n + 255) / 256, 256>>>();
    }

    constexpr int BM = 128, BN = 64, BK = 8, TM = 8, TN = 4;
    constexpr int THREADS = (BM / TM) * (BN / TN);   // 256

    // Pre-compute z_a for ALL timesteps: [T*B, M] = [8192,1024] @ [1000,1024]^T
    {
        dim3 grid((M_COLS + BN - 1) / BN, (T_STEPS * B_SZ) / BM, 1); // 16 x 64
        sgemm_nt_v2<BM, BN, BK, TM, TN><<<grid, THREADS>>>(
            T_STEPS * B_SZ, M_COLS, D_IN, D_IN, x, w_a, za, nullptr, 0);
    }

    // Sequential scan: z_b GEMM (split-K) + fused step
    {
        dim3 grid_zb((TC + BN - 1) / BN, B_SZ / BM, KSPLIT);  // 63 x 1 x 5
        const int kChunk = TC / KSPLIT;                        // 800
        for (int t = 0; t < T_STEPS; t++) {
            sgemm_nt_v2<BM, BN, BK, TM, TN><<<grid_zb, THREADS>>>(
                B_SZ, TC, TC, kChunk, psi, w_b, zbp, nullptr,
                (size_t)B_SZ * TC);
            rsm_step_kernel<<<B_SZ, 256>>>(t);
        }
    }

    // Decode ALL timesteps: out = ycol_all @ w_d^T + b_d  [8192,1024], K=1000
    {
        dim3 grid((D_OUT + BN - 1) / BN, (T_STEPS * B_SZ) / BM, 1);  // 16 x 64
        sgemm_nt_v2<BM, BN, BK, TM, TN><<<grid, THREADS>>>(
            T_STEPS * B_SZ, D_OUT, M_COLS, M_COLS, ycol, w_d, out, b_d, 0);
    }
}

// round 3
// speedup vs baseline: 24.3639x; 3.5831x over previous
#include <cuda_runtime.h>
#include <math.h>

// ---------------- problem constants ----------------
#define T_STEPS 64
#define B_SZ    128
#define M_COLS  1000
#define N_CELLS 4
#define TC      4000      // M_COLS * N_CELLS
#define K_TOP   25
#define D_IN    1024
#define D_OUT   1024

// ---------------- persistent device state ----------------
__device__ float g_psi [B_SZ * TC];                  // memory trace
__device__ float g_phi [B_SZ * TC];                  // inhibition trace
__device__ float g_zb  [B_SZ * TC];                  // incrementally maintained z_b
__device__ float g_za_all [T_STEPS * B_SZ * M_COLS]; // pre-computed feedforward drive
__device__ float g_ycol_all[T_STEPS * B_SZ * M_COLS];// column activity for decode
__device__ float g_wbt [TC * TC];                    // w_b transposed: g_wbt[j][n] = w_b[n][j]

// ---------------- init ----------------
__global__ void zero_state_kernel() {
    int i = blockIdx.x * blockDim.x + threadIdx.x;
    if (i < B_SZ * TC) { g_psi[i] = 0.f; g_phi[i] = 0.f; g_zb[i] = 0.f; }
}

// ---------------- 32x32 tiled transpose: out[j*TC+n] = in[n*TC+j] ----------------
__global__ void transpose_kernel(const float* __restrict__ in)
{
    __shared__ float tile[32][33];
    int x = blockIdx.x * 32 + threadIdx.x;
    int y = blockIdx.y * 32 + threadIdx.y;
#pragma unroll
    for (int j = 0; j < 32; j += 8)
        tile[threadIdx.y + j][threadIdx.x] = in[(size_t)(y + j) * TC + x];
    __syncthreads();
    x = blockIdx.y * 32 + threadIdx.x;
    y = blockIdx.x * 32 + threadIdx.y;
#pragma unroll
    for (int j = 0; j < 32; j += 8)
        g_wbt[(size_t)(y + j) * TC + x] = tile[threadIdx.x][threadIdx.y + j];
}

// ---------------- NT SGEMM (pre/post, batched over all timesteps) ----------------
// C[m,n] = sum_k A[m,k]*B[n,k] (+bias[n]). Mrows % BM == 0, Kdim % BK == 0.
template<int BM, int BN, int BK, int TM, int TN>
__global__ void __launch_bounds__((BM/TM)*(BN/TN))
sgemm_nt_v2(int Mrows, int Ncols, int Kdim,
            const float* __restrict__ A,
            const float* __restrict__ B,
            float* __restrict__ C,
            const float* __restrict__ bias)
{
    constexpr int THREADS = (BM / TM) * (BN / TN);
    __shared__ float As[BK][BM + 4];
    __shared__ float Bs[BK][BN + 4];

    const int tid = threadIdx.x;
    const int tn  = tid % (BN / TN);
    const int tm  = tid / (BN / TN);
    const int m0  = blockIdx.y * BM;
    const int n0  = blockIdx.x * BN;

    float acc[TM][TN];
#pragma unroll
    for (int i = 0; i < TM; i++)
#pragma unroll
        for (int j = 0; j < TN; j++) acc[i][j] = 0.f;

    constexpr int AQ = BK / 4;
    constexpr int A_LOADS = BM * AQ;
    constexpr int B_LOADS = BN * AQ;

    for (int k0 = 0; k0 < Kdim; k0 += BK) {
#pragma unroll
        for (int i = tid; i < A_LOADS; i += THREADS) {
            int row = i / AQ, q = i % AQ;
            float4 v = *reinterpret_cast<const float4*>(&A[(size_t)(m0 + row) * Kdim + k0 + q * 4]);
            As[q * 4 + 0][row] = v.x; As[q * 4 + 1][row] = v.y;
            As[q * 4 + 2][row] = v.z; As[q * 4 + 3][row] = v.w;
        }
#pragma unroll
        for (int i = tid; i < B_LOADS; i += THREADS) {
            int row = i / AQ, q = i % AQ;
            int gn = n0 + row;
            float4 v = make_float4(0.f, 0.f, 0.f, 0.f);
            if (gn < Ncols)
                v = *reinterpret_cast<const float4*>(&B[(size_t)gn * Kdim + k0 + q * 4]);
            Bs[q * 4 + 0][row] = v.x; Bs[q * 4 + 1][row] = v.y;
            Bs[q * 4 + 2][row] = v.z; Bs[q * 4 + 3][row] = v.w;
        }
        __syncthreads();

#pragma unroll
        for (int k = 0; k < BK; k++) {
            float4 a0 = *reinterpret_cast<const float4*>(&As[k][tm * TM]);
            float4 a1 = *reinterpret_cast<const float4*>(&As[k][tm * TM + 4]);
            float4 b0 = *reinterpret_cast<const float4*>(&Bs[k][tn * TN]);
            float a[TM]  = {a0.x, a0.y, a0.z, a0.w, a1.x, a1.y, a1.z, a1.w};
            float bb[TN] = {b0.x, b0.y, b0.z, b0.w};
#pragma unroll
            for (int i = 0; i < TM; i++)
#pragma unroll
                for (int j = 0; j < TN; j++)
                    acc[i][j] = fmaf(a[i], bb[j], acc[i][j]);
        }
        __syncthreads();
    }

#pragma unroll
    for (int i = 0; i < TM; i++) {
        int gm = m0 + tm * TM + i;
#pragma unroll
        for (int j = 0; j < TN; j++) {
            int gn = n0 + tn * TN + j;
            if (gn >= Ncols) continue;
            float v = acc[i][j];
            if (bias) v += bias[gn];
            C[(size_t)gm * Ncols + gn] = v;
        }
    }
}

// ---------------- fused RSM step + rank-25 z_b update ----------------
// one block (256 threads) per batch row
__global__ void __launch_bounds__(256) rsm_step_kernel(int t)
{
    const int b      = blockIdx.x;
    const int tid    = threadIdx.x;
    const int lane   = tid & 31;
    const int warpid = tid >> 5;

    __shared__ float         s_lam[M_COLS];   // column max of pi; reused for delta
    __shared__ float         s_sig[M_COLS];   // sigma at winner cell
    __shared__ unsigned char s_win[M_COLS];   // winner cell index
    __shared__ unsigned char s_sel[M_COLS];   // selected column flag
    __shared__ int           s_didx [K_TOP];  // winner cell global indices (sorted by column)
    __shared__ float         s_delta[K_TOP];  // delta values

    const float* zab  = g_za_all + ((size_t)t * B_SZ + b) * M_COLS;
    const float* phib = g_phi + b * TC;
    float*       zbb  = g_zb  + b * TC;

    // pass 1: per-column winner cell + column max of pi
    for (int c = tid; c < M_COLS; c += 256) {
        float zac = zab[c];
        float4 zb = *reinterpret_cast<const float4*>(&zbb[c * N_CELLS]);
        float4 ph = *reinterpret_cast<const float4*>(&phib[c * N_CELLS]);
        float sig[4] = {zac + zb.x, zac + zb.y, zac + zb.z, zac + zb.w};
        float pv [4] = {sig[0] * (1.f - ph.x), sig[1] * (1.f - ph.y),
                        sig[2] * (1.f - ph.z), sig[3] * (1.f - ph.w)};
        float best = pv[0]; int bw = 0;
#pragma unroll
        for (int n = 1; n < N_CELLS; n++)
            if (pv[n] > best) { best = pv[n]; bw = n; }   // strict > : first index wins
        s_lam[c] = best;
        s_win[c] = (unsigned char)bw;
        s_sig[c] = sig[bw];
        s_sel[c] = 0;
    }
    __syncthreads();

    // pass 2: iterative top-K by warp 0 only (value desc, index asc on ties)
    if (warpid == 0) {
        for (int it = 0; it < K_TOP; it++) {
            float v  = -INFINITY;
            int   vi = 0x7fffffff;
            for (int c = lane; c < M_COLS; c += 32) {
                float l = s_lam[c];
                if (l > v || (l == v && c < vi)) { v = l; vi = c; }
            }
#pragma unroll
            for (int off = 16; off > 0; off >>= 1) {
                float ov = __shfl_down_sync(0xffffffffu, v, off);
                int   oi = __shfl_down_sync(0xffffffffu, vi, off);
                if (ov > v || (ov == v && oi < vi)) { v = ov; vi = oi; }
            }
            vi = __shfl_sync(0xffffffffu, vi, 0);
            if (lane == 0) s_sel[vi] = 1;
            s_lam[vi] = -INFINITY;   // all lanes write same value (benign)
            __syncwarp();
        }
    }
    __syncthreads();

    // pass 3: activation, y_col, trace updates, delta for winner cells
    float* psib  = g_psi + b * TC;
    float* phiw  = g_phi + b * TC;
    float* ycolb = g_ycol_all + ((size_t)t * B_SZ + b) * M_COLS;
    for (int c = tid; c < M_COLS; c += 256) {
        float y   = 0.f;
        int   w   = s_win[c];
        int   sel = s_sel[c];
        if (sel) y = tanhf(s_sig[c]);
        ycolb[c] = fmaxf(y, 0.f);
        float4 ps = *reinterpret_cast<const float4*>(&psib[c * N_CELLS]);
        float4 ph = *reinterpret_cast<const float4*>(&phiw[c * N_CELLS]);
        float pso[4] = {ps.x, ps.y, ps.z, ps.w};
        float pho[4] = {ph.x, ph.y, ph.z, ph.w};
        // delta = max(y - 0.5*psi_old, 0) at the winner cell of a selected column
        if (sel) s_lam[c] = fmaxf(y - 0.5f * pso[w], 0.f);
#pragma unroll
        for (int n = 0; n < N_CELLS; n++) {
            float yc = (sel && n == w) ? y : 0.f;
            pso[n] = fmaxf(pso[n] * 0.5f, yc);   // EPS   = 0.5
            pho[n] = fmaxf(pho[n] * 0.5f, yc);   // GAMMA = 0.5
        }
        *reinterpret_cast<float4*>(&psib[c * N_CELLS]) =
            make_float4(pso[0], pso[1], pso[2], pso[3]);
        *reinterpret_cast<float4*>(&phiw[c * N_CELLS]) =
            make_float4(pho[0], pho[1], pho[2], pho[3]);
    }
    __syncthreads();

    // pass 4a: warp 0 compacts selected columns (ascending order -> deterministic)
    if (warpid == 0) {
        int cnt = 0;
        for (int base = 0; base < M_COLS; base += 32) {
            int c = base + lane;
            bool sel = (c < M_COLS) && s_sel[c];
            unsigned mask = __ballot_sync(0xffffffffu, sel);
            if (sel) {
                int pos = cnt + __popc(mask & ((1u << lane) - 1u));
                s_didx [pos] = c * N_CELLS + (int)s_win[c];
                s_delta[pos] = s_lam[c];
            }
            cnt += __popc(mask);
        }
    }
    __syncthreads();

    // pass 4b: rank-K_TOP update of z_b for the next step (deterministic order)
    for (int q = tid; q < TC / 4; q += 256) {
        float4 z = *reinterpret_cast<const float4*>(&zbb[q * 4]);
        float4 acc = make_float4(0.5f * z.x, 0.5f * z.y, 0.5f * z.z, 0.5f * z.w);
#pragma unroll
        for (int i = 0; i < K_TOP; i++) {
            float d = s_delta[i];
            const float4 wrow = *reinterpret_cast<const float4*>(
                &g_wbt[(size_t)s_didx[i] * TC + q * 4]);
            acc.x = fmaf(d, wrow.x, acc.x);
            acc.y = fmaf(d, wrow.y, acc.y);
            acc.z = fmaf(d, wrow.z, acc.z);
            acc.w = fmaf(d, wrow.w, acc.w);
        }
        *reinterpret_cast<float4*>(&zbb[q * 4]) = acc;
    }
}

// ---------------- host launch ----------------
extern "C" void kernel_launch(void* const* d_in, const int* in_sizes, int n_in,
                              void* d_out, int out_size)
{
    const float* x   = (const float*)d_in[0];   // [T, B, D_IN]
    const float* w_a = (const float*)d_in[1];   // [M, D_IN]
    const float* w_b = (const float*)d_in[2];   // [TC, TC]
    const float* w_d = (const float*)d_in[3];   // [D_OUT, M]
    const float* b_d = (const float*)d_in[4];   // [D_OUT]
    float* out = (float*)d_out;                 // [T, B, D_OUT]

    float *za, *ycol;
    cudaGetSymbolAddress((void**)&za,   g_za_all);
    cudaGetSymbolAddress((void**)&ycol, g_ycol_all);

    {
        int n = B_SZ * TC;
        zero_state_kernel<<<(n + 255) / 256, 256>>>();
    }

    // transpose w_b -> g_wbt (columns become contiguous rows)
    {
        dim3 grid(TC / 32, TC / 32);
        transpose_kernel<<<grid, dim3(32, 8)>>>(w_b);
    }

    constexpr int BM = 128, BN = 64, BK = 8, TM = 8, TN = 4;
    constexpr int THREADS = (BM / TM) * (BN / TN);   // 256

    // Pre-compute z_a for ALL timesteps: [8192,1000] = [8192,1024] @ [1000,1024]^T
    {
        dim3 grid((M_COLS + BN - 1) / BN, (T_STEPS * B_SZ) / BM); // 16 x 64
        sgemm_nt_v2<BM, BN, BK, TM, TN><<<grid, THREADS>>>(
            T_STEPS * B_SZ, M_COLS, D_IN, x, w_a, za, nullptr);
    }

    // Sequential scan: fused step + rank-25 z_b update (one kernel per step)
    for (int t = 0; t < T_STEPS; t++)
        rsm_step_kernel<<<B_SZ, 256>>>(t);

    // Decode ALL timesteps: out = ycol_all @ w_d^T + b_d  [8192,1024], K=1000
    {
        dim3 grid((D_OUT + BN - 1) / BN, (T_STEPS * B_SZ) / BM);  // 16 x 64
        sgemm_nt_v2<BM, BN, BK, TM, TN><<<grid, THREADS>>>(
            T_STEPS * B_SZ, D_OUT, M_COLS, ycol, w_d, out, b_d);
    }
}

// round 4
// speedup vs baseline: 30.1084x; 1.2358x over previous
#include <cuda_runtime.h>
#include <math.h>

// ---------------- problem constants ----------------
#define T_STEPS 64
#define B_SZ    128
#define M_COLS  1000
#define N_CELLS 4
#define TC      4000      // M_COLS * N_CELLS
#define K_TOP   25
#define D_IN    1024
#define D_OUT   1024

// ---------------- persistent device state ----------------
__device__ float g_psi [B_SZ * TC];                  // memory trace
__device__ float g_phi [B_SZ * TC];                  // inhibition trace
__device__ float g_zb  [B_SZ * TC];                  // incrementally maintained z_b
__device__ float g_za_all [T_STEPS * B_SZ * M_COLS]; // pre-computed feedforward drive
__device__ float g_wbt [TC * TC];                    // w_b transposed
__device__ float g_wdt [M_COLS * D_OUT];             // w_d transposed: [c][d]
__device__ int   g_didx [B_SZ * K_TOP];              // winner cell global idx (per step)
__device__ float g_delta[B_SZ * K_TOP];              // delta values (per step)
__device__ int   g_ycidx[T_STEPS * B_SZ * K_TOP];    // selected column indices (all steps)
__device__ float g_ycval[T_STEPS * B_SZ * K_TOP];    // max(y,0) at those columns

// ---------------- init ----------------
__global__ void zero_state_kernel() {
    int i = blockIdx.x * blockDim.x + threadIdx.x;
    if (i < B_SZ * TC) { g_psi[i] = 0.f; g_phi[i] = 0.f; g_zb[i] = 0.f; }
}

// ---------------- generic 32x32 tiled transpose with bounds ----------------
// out[c * outStride + r] = in[r * inStride + c], r < rows, c < cols
__global__ void transpose_kernel(const float* __restrict__ in, float* __restrict__ out,
                                 int rows, int cols)
{
    __shared__ float tile[32][33];
    int c0 = blockIdx.x * 32, r0 = blockIdx.y * 32;
#pragma unroll
    for (int j = 0; j < 32; j += 8) {
        int r = r0 + threadIdx.y + j, c = c0 + threadIdx.x;
        if (r < rows && c < cols)
            tile[threadIdx.y + j][threadIdx.x] = in[(size_t)r * cols + c];
    }
    __syncthreads();
#pragma unroll
    for (int j = 0; j < 32; j += 8) {
        int c = c0 + threadIdx.y + j, r = r0 + threadIdx.x;
        if (r < rows && c < cols)
            out[(size_t)c * rows + r] = tile[threadIdx.x][threadIdx.y + j];
    }
}

// ---------------- NT SGEMM (pre-GEMM for z_a) ----------------
template<int BM, int BN, int BK, int TM, int TN>
__global__ void __launch_bounds__((BM/TM)*(BN/TN))
sgemm_nt_v2(int Mrows, int Ncols, int Kdim,
            const float* __restrict__ A,
            const float* __restrict__ B,
            float* __restrict__ C)
{
    constexpr int THREADS = (BM / TM) * (BN / TN);
    __shared__ float As[BK][BM + 4];
    __shared__ float Bs[BK][BN + 4];

    const int tid = threadIdx.x;
    const int tn  = tid % (BN / TN);
    const int tm  = tid / (BN / TN);
    const int m0  = blockIdx.y * BM;
    const int n0  = blockIdx.x * BN;

    float acc[TM][TN];
#pragma unroll
    for (int i = 0; i < TM; i++)
#pragma unroll
        for (int j = 0; j < TN; j++) acc[i][j] = 0.f;

    constexpr int AQ = BK / 4;
    constexpr int A_LOADS = BM * AQ;
    constexpr int B_LOADS = BN * AQ;

    for (int k0 = 0; k0 < Kdim; k0 += BK) {
#pragma unroll
        for (int i = tid; i < A_LOADS; i += THREADS) {
            int row = i / AQ, q = i % AQ;
            float4 v = *reinterpret_cast<const float4*>(&A[(size_t)(m0 + row) * Kdim + k0 + q * 4]);
            As[q * 4 + 0][row] = v.x; As[q * 4 + 1][row] = v.y;
            As[q * 4 + 2][row] = v.z; As[q * 4 + 3][row] = v.w;
        }
#pragma unroll
        for (int i = tid; i < B_LOADS; i += THREADS) {
            int row = i / AQ, q = i % AQ;
            int gn = n0 + row;
            float4 v = make_float4(0.f, 0.f, 0.f, 0.f);
            if (gn < Ncols)
                v = *reinterpret_cast<const float4*>(&B[(size_t)gn * Kdim + k0 + q * 4]);
            Bs[q * 4 + 0][row] = v.x; Bs[q * 4 + 1][row] = v.y;
            Bs[q * 4 + 2][row] = v.z; Bs[q * 4 + 3][row] = v.w;
        }
        __syncthreads();

#pragma unroll
        for (int k = 0; k < BK; k++) {
            float4 a0 = *reinterpret_cast<const float4*>(&As[k][tm * TM]);
            float4 a1 = *reinterpret_cast<const float4*>(&As[k][tm * TM + 4]);
            float4 b0 = *reinterpret_cast<const float4*>(&Bs[k][tn * TN]);
            float a[TM]  = {a0.x, a0.y, a0.z, a0.w, a1.x, a1.y, a1.z, a1.w};
            float bb[TN] = {b0.x, b0.y, b0.z, b0.w};
#pragma unroll
            for (int i = 0; i < TM; i++)
#pragma unroll
                for (int j = 0; j < TN; j++)
                    acc[i][j] = fmaf(a[i], bb[j], acc[i][j]);
        }
        __syncthreads();
    }

#pragma unroll
    for (int i = 0; i < TM; i++) {
        int gm = m0 + tm * TM + i;
#pragma unroll
        for (int j = 0; j < TN; j++) {
            int gn = n0 + tn * TN + j;
            if (gn >= Ncols) continue;
            C[(size_t)gm * Ncols + gn] = acc[i][j];
        }
    }
}

// ---------------- kernel A: sequential RSM logic (one block per batch row) -------
__global__ void __launch_bounds__(256) rsm_select_kernel(int t)
{
    const int b      = blockIdx.x;
    const int tid    = threadIdx.x;
    const int lane   = tid & 31;
    const int warpid = tid >> 5;

    __shared__ float         s_lam[M_COLS];   // column max of pi; reused for delta
    __shared__ float         s_sig[M_COLS];   // sigma at winner; then y at winner
    __shared__ unsigned char s_win[M_COLS];
    __shared__ unsigned char s_sel[M_COLS];

    const float* zab  = g_za_all + ((size_t)t * B_SZ + b) * M_COLS;
    const float* phib = g_phi + b * TC;
    const float* zbb  = g_zb  + b * TC;

    // pass 1: per-column winner cell + column max of pi
#pragma unroll 4
    for (int c = tid; c < M_COLS; c += 256) {
        float zac = zab[c];
        float4 zb = *reinterpret_cast<const float4*>(&zbb[c * N_CELLS]);
        float4 ph = *reinterpret_cast<const float4*>(&phib[c * N_CELLS]);
        float sig[4] = {zac + zb.x, zac + zb.y, zac + zb.z, zac + zb.w};
        float pv [4] = {sig[0] * (1.f - ph.x), sig[1] * (1.f - ph.y),
                        sig[2] * (1.f - ph.z), sig[3] * (1.f - ph.w)};
        float best = pv[0]; int bw = 0;
#pragma unroll
        for (int n = 1; n < N_CELLS; n++)
            if (pv[n] > best) { best = pv[n]; bw = n; }
        s_lam[c] = best;
        s_win[c] = (unsigned char)bw;
        s_sig[c] = sig[bw];
        s_sel[c] = 0;
    }
    __syncthreads();

    // pass 2: iterative top-K by warp 0 (value desc, index asc on ties)
    if (warpid == 0) {
        for (int it = 0; it < K_TOP; it++) {
            float v  = -INFINITY;
            int   vi = 0x7fffffff;
            for (int c = lane; c < M_COLS; c += 32) {
                float l = s_lam[c];
                if (l > v || (l == v && c < vi)) { v = l; vi = c; }
            }
#pragma unroll
            for (int off = 16; off > 0; off >>= 1) {
                float ov = __shfl_down_sync(0xffffffffu, v, off);
                int   oi = __shfl_down_sync(0xffffffffu, vi, off);
                if (ov > v || (ov == v && oi < vi)) { v = ov; vi = oi; }
            }
            vi = __shfl_sync(0xffffffffu, vi, 0);
            if (lane == 0) s_sel[vi] = 1;
            s_lam[vi] = -INFINITY;
            __syncwarp();
        }
    }
    __syncthreads();

    // pass 3: activation, trace updates, delta and y for winner cells
    float* psib = g_psi + b * TC;
    float* phiw = g_phi + b * TC;
#pragma unroll 4
    for (int c = tid; c < M_COLS; c += 256) {
        int w   = s_win[c];
        int sel = s_sel[c];
        float4 ps = *reinterpret_cast<const float4*>(&psib[c * N_CELLS]);
        float4 ph = *reinterpret_cast<const float4*>(&phiw[c * N_CELLS]);
        float pso[4] = {ps.x, ps.y, ps.z, ps.w};
        float pho[4] = {ph.x, ph.y, ph.z, ph.w};
        float y = 0.f;
        if (sel) {
            y = tanhf(s_sig[c]);
            s_sig[c] = y;                                  // stash y for compaction
            s_lam[c] = fmaxf(y - 0.5f * pso[w], 0.f);      // delta
        }
#pragma unroll
        for (int n = 0; n < N_CELLS; n++) {
            float yc = (sel && n == w) ? y : 0.f;
            pso[n] = fmaxf(pso[n] * 0.5f, yc);   // EPS   = 0.5
            pho[n] = fmaxf(pho[n] * 0.5f, yc);   // GAMMA = 0.5
        }
        *reinterpret_cast<float4*>(&psib[c * N_CELLS]) =
            make_float4(pso[0], pso[1], pso[2], pso[3]);
        *reinterpret_cast<float4*>(&phiw[c * N_CELLS]) =
            make_float4(pho[0], pho[1], pho[2], pho[3]);
    }
    __syncthreads();

    // pass 4: warp 0 compacts selected columns (ascending => deterministic)
    if (warpid == 0) {
        int cnt = 0;
        int*   didx  = g_didx  + b * K_TOP;
        float* delta = g_delta + b * K_TOP;
        int*   ycidx = g_ycidx + ((size_t)t * B_SZ + b) * K_TOP;
        float* ycval = g_ycval + ((size_t)t * B_SZ + b) * K_TOP;
        for (int base = 0; base < M_COLS; base += 32) {
            int c = base + lane;
            bool sel = (c < M_COLS) && s_sel[c];
            unsigned mask = __ballot_sync(0xffffffffu, sel);
            if (sel) {
                int pos = cnt + __popc(mask & ((1u << lane) - 1u));
                didx [pos] = c * N_CELLS + (int)s_win[c];
                delta[pos] = s_lam[c];
                ycidx[pos] = c;
                ycval[pos] = fmaxf(s_sig[c], 0.f);
            }
            cnt += __popc(mask);
        }
    }
}

// ---------------- kernel B: rank-25 z_b update (wide grid) ----------------
// grid (4, B_SZ), 256 threads; block x covers 250 float4s of one batch row
__global__ void __launch_bounds__(256) rsm_zb_update_kernel()
{
    const int b   = blockIdx.y;
    const int tid = threadIdx.x;

    __shared__ int   s_idx [K_TOP];
    __shared__ float s_dlt [K_TOP];
    if (tid < K_TOP) {
        s_idx[tid] = g_didx [b * K_TOP + tid];
        s_dlt[tid] = g_delta[b * K_TOP + tid];
    }
    __syncthreads();

    const int q = blockIdx.x * 250 + tid;    // float4 index within row
    if (q >= TC / 4) return;

    float* zbb = g_zb + b * TC;
    float4 z = *reinterpret_cast<const float4*>(&zbb[q * 4]);
    float4 acc = make_float4(0.5f * z.x, 0.5f * z.y, 0.5f * z.z, 0.5f * z.w);
#pragma unroll
    for (int i = 0; i < K_TOP; i++) {
        float d = s_dlt[i];
        const float4 wrow = *reinterpret_cast<const float4*>(
            &g_wbt[(size_t)s_idx[i] * TC + q * 4]);
        acc.x = fmaf(d, wrow.x, acc.x);
        acc.y = fmaf(d, wrow.y, acc.y);
        acc.z = fmaf(d, wrow.z, acc.z);
        acc.w = fmaf(d, wrow.w, acc.w);
    }
    *reinterpret_cast<float4*>(&zbb[q * 4]) = acc;
}

// ---------------- sparse decode: out[tb] = b_d + sum_i y_i * w_dT[c_i] ----------
// grid T*B blocks, 256 threads; each thread computes one float4 of the output row
__global__ void __launch_bounds__(256) decode_kernel(const float* __restrict__ b_d,
                                                     float* __restrict__ out)
{
    const int tb  = blockIdx.x;
    const int tid = threadIdx.x;

    __shared__ int   s_c[K_TOP];
    __shared__ float s_y[K_TOP];
    if (tid < K_TOP) {
        s_c[tid] = g_ycidx[(size_t)tb * K_TOP + tid];
        s_y[tid] = g_ycval[(size_t)tb * K_TOP + tid];
    }
    __syncthreads();

    float4 acc = *reinterpret_cast<const float4*>(&b_d[tid * 4]);
#pragma unroll
    for (int i = 0; i < K_TOP; i++) {
        float y = s_y[i];
        const float4 w = *reinterpret_cast<const float4*>(
            &g_wdt[(size_t)s_c[i] * D_OUT + tid * 4]);
        acc.x = fmaf(y, w.x, acc.x);
        acc.y = fmaf(y, w.y, acc.y);
        acc.z = fmaf(y, w.z, acc.z);
        acc.w = fmaf(y, w.w, acc.w);
    }
    *reinterpret_cast<float4*>(&out[(size_t)tb * D_OUT + tid * 4]) = acc;
}

// ---------------- host launch ----------------
extern "C" void kernel_launch(void* const* d_in, const int* in_sizes, int n_in,
                              void* d_out, int out_size)
{
    const float* x   = (const float*)d_in[0];   // [T, B, D_IN]
    const float* w_a = (const float*)d_in[1];   // [M, D_IN]
    const float* w_b = (const float*)d_in[2];   // [TC, TC]
    const float* w_d = (const float*)d_in[3];   // [D_OUT, M]
    const float* b_d = (const float*)d_in[4];   // [D_OUT]
    float* out = (float*)d_out;                 // [T, B, D_OUT]

    float *za, *wbt, *wdt;
    cudaGetSymbolAddress((void**)&za,  g_za_all);
    cudaGetSymbolAddress((void**)&wbt, g_wbt);
    cudaGetSymbolAddress((void**)&wdt, g_wdt);

    {
        int n = B_SZ * TC;
        zero_state_kernel<<<(n + 255) / 256, 256>>>();
    }

    // transpose w_b (4000x4000) and w_d (1024x1000)
    transpose_kernel<<<dim3(TC / 32, TC / 32), dim3(32, 8)>>>(w_b, wbt, TC, TC);
    transpose_kernel<<<dim3((M_COLS + 31) / 32, D_OUT / 32), dim3(32, 8)>>>(
        w_d, wdt, D_OUT, M_COLS);

    constexpr int BM = 128, BN = 64, BK = 8, TM = 8, TN = 4;
    constexpr int THREADS = (BM / TM) * (BN / TN);   // 256

    // Pre-compute z_a for ALL timesteps: [8192,1000] = [8192,1024] @ [1000,1024]^T
    {
        dim3 grid((M_COLS + BN - 1) / BN, (T_STEPS * B_SZ) / BM); // 16 x 64
        sgemm_nt_v2<BM, BN, BK, TM, TN><<<grid, THREADS>>>(
            T_STEPS * B_SZ, M_COLS, D_IN, x, w_a, za);
    }

    // Sequential scan: select (grid 128) + wide rank-25 z_b update (grid 4x128)
    for (int t = 0; t < T_STEPS; t++) {
        rsm_select_kernel<<<B_SZ, 256>>>(t);
        rsm_zb_update_kernel<<<dim3(4, B_SZ), 256>>>();
    }

    // Sparse decode for all timesteps
    decode_kernel<<<T_STEPS * B_SZ, 256>>>(b_d, out);
}

// round 5
// speedup vs baseline: 51.0630x; 1.6960x over previous
#include <cuda_runtime.h>
#include <math.h>

// ---------------- problem constants ----------------
#define T_STEPS 64
#define B_SZ    128
#define M_COLS  1000
#define N_CELLS 4
#define TC      4000      // M_COLS * N_CELLS
#define K_TOP   25
#define D_IN    1024
#define D_OUT   1024

// ---------------- persistent device state ----------------
__device__ float g_za_all[T_STEPS * B_SZ * M_COLS]; // pre-computed feedforward drive
__device__ float g_wbt  [TC * TC];                  // w_b transposed
__device__ float g_wdt  [M_COLS * D_OUT];           // w_d transposed
__device__ int   g_ycidx[T_STEPS * B_SZ * K_TOP];   // selected columns per (t,b)
__device__ float g_ycval[T_STEPS * B_SZ * K_TOP];   // max(y,0) per (t,b)

// ---------------- generic 32x32 tiled transpose with bounds ----------------
__global__ void transpose_kernel(const float* __restrict__ in, float* __restrict__ out,
                                 int rows, int cols)
{
    __shared__ float tile[32][33];
    int c0 = blockIdx.x * 32, r0 = blockIdx.y * 32;
#pragma unroll
    for (int j = 0; j < 32; j += 8) {
        int r = r0 + threadIdx.y + j, c = c0 + threadIdx.x;
        if (r < rows && c < cols)
            tile[threadIdx.y + j][threadIdx.x] = in[(size_t)r * cols + c];
    }
    __syncthreads();
#pragma unroll
    for (int j = 0; j < 32; j += 8) {
        int c = c0 + threadIdx.y + j, r = r0 + threadIdx.x;
        if (r < rows && c < cols)
            out[(size_t)c * rows + r] = tile[threadIdx.x][threadIdx.y + j];
    }
}

// ---------------- NT SGEMM (pre-GEMM for z_a), BK=16 ----------------
template<int BM, int BN, int BK, int TM, int TN>
__global__ void __launch_bounds__((BM/TM)*(BN/TN))
sgemm_nt_v2(int Mrows, int Ncols, int Kdim,
            const float* __restrict__ A,
            const float* __restrict__ B,
            float* __restrict__ C)
{
    constexpr int THREADS = (BM / TM) * (BN / TN);
    __shared__ float As[BK][BM + 4];
    __shared__ float Bs[BK][BN + 4];

    const int tid = threadIdx.x;
    const int tn  = tid % (BN / TN);
    const int tm  = tid / (BN / TN);
    const int m0  = blockIdx.y * BM;
    const int n0  = blockIdx.x * BN;

    float acc[TM][TN];
#pragma unroll
    for (int i = 0; i < TM; i++)
#pragma unroll
        for (int j = 0; j < TN; j++) acc[i][j] = 0.f;

    constexpr int AQ = BK / 4;
    constexpr int A_LOADS = BM * AQ;
    constexpr int B_LOADS = BN * AQ;

    for (int k0 = 0; k0 < Kdim; k0 += BK) {
#pragma unroll
        for (int i = tid; i < A_LOADS; i += THREADS) {
            int row = i / AQ, q = i % AQ;
            float4 v = *reinterpret_cast<const float4*>(&A[(size_t)(m0 + row) * Kdim + k0 + q * 4]);
            As[q * 4 + 0][row] = v.x; As[q * 4 + 1][row] = v.y;
            As[q * 4 + 2][row] = v.z; As[q * 4 + 3][row] = v.w;
        }
#pragma unroll
        for (int i = tid; i < B_LOADS; i += THREADS) {
            int row = i / AQ, q = i % AQ;
            int gn = n0 + row;
            float4 v = make_float4(0.f, 0.f, 0.f, 0.f);
            if (gn < Ncols)
                v = *reinterpret_cast<const float4*>(&B[(size_t)gn * Kdim + k0 + q * 4]);
            Bs[q * 4 + 0][row] = v.x; Bs[q * 4 + 1][row] = v.y;
            Bs[q * 4 + 2][row] = v.z; Bs[q * 4 + 3][row] = v.w;
        }
        __syncthreads();

#pragma unroll
        for (int k = 0; k < BK; k++) {
            float4 a0 = *reinterpret_cast<const float4*>(&As[k][tm * TM]);
            float4 a1 = *reinterpret_cast<const float4*>(&As[k][tm * TM + 4]);
            float4 b0 = *reinterpret_cast<const float4*>(&Bs[k][tn * TN]);
            float a[TM]  = {a0.x, a0.y, a0.z, a0.w, a1.x, a1.y, a1.z, a1.w};
            float bb[TN] = {b0.x, b0.y, b0.z, b0.w};
#pragma unroll
            for (int i = 0; i < TM; i++)
#pragma unroll
                for (int j = 0; j < TN; j++)
                    acc[i][j] = fmaf(a[i], bb[j], acc[i][j]);
        }
        __syncthreads();
    }

#pragma unroll
    for (int i = 0; i < TM; i++) {
        int gm = m0 + tm * TM + i;
#pragma unroll
        for (int j = 0; j < TN; j++) {
            int gn = n0 + tn * TN + j;
            if (gn >= Ncols) continue;
            C[(size_t)gm * Ncols + gn] = acc[i][j];
        }
    }
}

// ---------------- persistent scan kernel: one block per batch row ----------------
// All 64 timesteps run inside the kernel. State (psi == phi, z_b) lives in SMEM.
__global__ void __launch_bounds__(512) rsm_scan_kernel()
{
    const int b      = blockIdx.x;
    const int tid    = threadIdx.x;
    const int lane   = tid & 31;
    const int warpid = tid >> 5;

    __shared__ float         s_psi[TC];        // 16 KB  (psi == phi since EPS==GAMMA)
    __shared__ float         s_zb [TC];        // 16 KB  incrementally maintained z_b
    __shared__ float         s_lam[M_COLS];    // 4 KB   column max of pi
    __shared__ float         s_sig[M_COLS];    // 4 KB   sigma at winner cell
    __shared__ float         s_yw [M_COLS];    // 4 KB   y at winner (dense, cleared per step)
    __shared__ unsigned char s_win[M_COLS];    // 1 KB   winner cell per column
    __shared__ int           s_wincol[K_TOP];  // selected columns (selection order)
    __shared__ int           s_didx [K_TOP];   // winner cell global idx
    __shared__ float         s_delta[K_TOP];   // delta values

    // init state
    for (int i = tid; i < TC; i += 512) { s_psi[i] = 0.f; s_zb[i] = 0.f; }
    __syncthreads();

    for (int t = 0; t < T_STEPS; t++) {
        const float* zab = g_za_all + ((size_t)t * B_SZ + b) * M_COLS;

        // ---- phase A: per-column winner + column max of pi (phi == psi) ----
        for (int c = tid; c < M_COLS; c += 512) {
            float  zac = zab[c];
            float4 zb  = *reinterpret_cast<const float4*>(&s_zb [c * 4]);
            float4 ph  = *reinterpret_cast<const float4*>(&s_psi[c * 4]);
            float sig[4] = {zac + zb.x, zac + zb.y, zac + zb.z, zac + zb.w};
            float pv [4] = {sig[0] * (1.f - ph.x), sig[1] * (1.f - ph.y),
                            sig[2] * (1.f - ph.z), sig[3] * (1.f - ph.w)};
            float best = pv[0]; int bw = 0;
#pragma unroll
            for (int n = 1; n < N_CELLS; n++)
                if (pv[n] > best) { best = pv[n]; bw = n; }   // first index wins ties
            s_lam[c] = best;
            s_win[c] = (unsigned char)bw;
            s_sig[c] = sig[bw];
            s_yw [c] = 0.f;
        }
        __syncthreads();

        // ---- phase T: top-K by warp 0, register-resident (value desc, idx asc) ----
        if (warpid == 0) {
            float v[32];
#pragma unroll
            for (int j = 0; j < 32; j++) {
                int c = j * 32 + lane;
                v[j] = (c < M_COLS) ? s_lam[c] : -INFINITY;
            }
            for (int it = 0; it < K_TOP; it++) {
                float bv = v[0]; int bj = 0;
#pragma unroll
                for (int j = 1; j < 32; j++)
                    if (v[j] > bv) { bv = v[j]; bj = j; }     // smaller j (=col) on tie
                int bc = bj * 32 + lane;
#pragma unroll
                for (int off = 16; off > 0; off >>= 1) {
                    float ov = __shfl_down_sync(0xffffffffu, bv, off);
                    int   oc = __shfl_down_sync(0xffffffffu, bc, off);
                    if (ov > bv || (ov == bv && oc < bc)) { bv = ov; bc = oc; }
                }
                bc = __shfl_sync(0xffffffffu, bc, 0);
                if ((bc & 31) == lane) {
                    int jw = bc >> 5;
#pragma unroll
                    for (int j = 0; j < 32; j++)
                        if (j == jw) v[j] = -INFINITY;
                }
                if (lane == 0) s_wincol[it] = bc;
            }
            __syncwarp();

            // ---- emit: lanes 0..24 handle one winner each ----
            if (lane < K_TOP) {
                int   c    = s_wincol[lane];
                int   w    = (int)s_win[c];
                int   cell = c * N_CELLS + w;
                float y    = tanhf(s_sig[c]);
                s_didx [lane] = cell;
                s_delta[lane] = fmaxf(y - 0.5f * s_psi[cell], 0.f);
                s_yw[c] = y;
                size_t o = ((size_t)t * B_SZ + b) * K_TOP + lane;
                g_ycidx[o] = c;
                g_ycval[o] = fmaxf(y, 0.f);
            }
        }
        __syncthreads();

        if (t == T_STEPS - 1) break;   // no state needed after last step

        // ---- phase B: rank-25 z_b update + psi decay/winner-max ----
        for (int c = tid; c < M_COLS; c += 512) {
            float4 z   = *reinterpret_cast<const float4*>(&s_zb[c * 4]);
            float4 acc = make_float4(0.5f * z.x, 0.5f * z.y, 0.5f * z.z, 0.5f * z.w);
#pragma unroll
            for (int i = 0; i < K_TOP; i++) {
                float d = s_delta[i];
                const float4 wr = *reinterpret_cast<const float4*>(
                    &g_wbt[(size_t)s_didx[i] * TC + c * 4]);
                acc.x = fmaf(d, wr.x, acc.x);
                acc.y = fmaf(d, wr.y, acc.y);
                acc.z = fmaf(d, wr.z, acc.z);
                acc.w = fmaf(d, wr.w, acc.w);
            }
            *reinterpret_cast<float4*>(&s_zb[c * 4]) = acc;

            float4 p = *reinterpret_cast<const float4*>(&s_psi[c * 4]);
            p.x *= 0.5f; p.y *= 0.5f; p.z *= 0.5f; p.w *= 0.5f;
            float y = s_yw[c];
            if (y > 0.f) {
                int w = (int)s_win[c];
                if      (w == 0) p.x = fmaxf(p.x, y);
                else if (w == 1) p.y = fmaxf(p.y, y);
                else if (w == 2) p.z = fmaxf(p.z, y);
                else             p.w = fmaxf(p.w, y);
            }
            *reinterpret_cast<float4*>(&s_psi[c * 4]) = p;
        }
        __syncthreads();
    }
}

// ---------------- sparse decode: out[tb] = b_d + sum_i y_i * w_dT[c_i] ----------
__global__ void __launch_bounds__(256) decode_kernel(const float* __restrict__ b_d,
                                                     float* __restrict__ out)
{
    const int tb  = blockIdx.x;
    const int tid = threadIdx.x;

    __shared__ int   s_c[K_TOP];
    __shared__ float s_y[K_TOP];
    if (tid < K_TOP) {
        s_c[tid] = g_ycidx[(size_t)tb * K_TOP + tid];
        s_y[tid] = g_ycval[(size_t)tb * K_TOP + tid];
    }
    __syncthreads();

    float4 acc = *reinterpret_cast<const float4*>(&b_d[tid * 4]);
#pragma unroll
    for (int i = 0; i < K_TOP; i++) {
        float y = s_y[i];
        const float4 w = *reinterpret_cast<const float4*>(
            &g_wdt[(size_t)s_c[i] * D_OUT + tid * 4]);
        acc.x = fmaf(y, w.x, acc.x);
        acc.y = fmaf(y, w.y, acc.y);
        acc.z = fmaf(y, w.z, acc.z);
        acc.w = fmaf(y, w.w, acc.w);
    }
    *reinterpret_cast<float4*>(&out[(size_t)tb * D_OUT + tid * 4]) = acc;
}

// ---------------- host launch ----------------
extern "C" void kernel_launch(void* const* d_in, const int* in_sizes, int n_in,
                              void* d_out, int out_size)
{
    const float* x   = (const float*)d_in[0];   // [T, B, D_IN]
    const float* w_a = (const float*)d_in[1];   // [M, D_IN]
    const float* w_b = (const float*)d_in[2];   // [TC, TC]
    const float* w_d = (const float*)d_in[3];   // [D_OUT, M]
    const float* b_d = (const float*)d_in[4];   // [D_OUT]
    float* out = (float*)d_out;                 // [T, B, D_OUT]

    float *za, *wbt, *wdt;
    cudaGetSymbolAddress((void**)&za,  g_za_all);
    cudaGetSymbolAddress((void**)&wbt, g_wbt);
    cudaGetSymbolAddress((void**)&wdt, g_wdt);

    // transpose w_b (4000x4000) and w_d (1024x1000)
    transpose_kernel<<<dim3(TC / 32, TC / 32), dim3(32, 8)>>>(w_b, wbt, TC, TC);
    transpose_kernel<<<dim3((M_COLS + 31) / 32, D_OUT / 32), dim3(32, 8)>>>(
        w_d, wdt, D_OUT, M_COLS);

    constexpr int BM = 128, BN = 64, BK = 16, TM = 8, TN = 4;
    constexpr int THREADS = (BM / TM) * (BN / TN);   // 256

    // Pre-compute z_a for ALL timesteps: [8192,1000] = [8192,1024] @ [1000,1024]^T
    {
        dim3 grid((M_COLS + BN - 1) / BN, (T_STEPS * B_SZ) / BM); // 16 x 64
        sgemm_nt_v2<BM, BN, BK, TM, TN><<<grid, THREADS>>>(
            T_STEPS * B_SZ, M_COLS, D_IN, x, w_a, za);
    }

    // Entire 64-step scan in ONE persistent kernel (one block per batch row)
    rsm_scan_kernel<<<B_SZ, 512>>>();

    // Sparse decode for all timesteps
    decode_kernel<<<T_STEPS * B_SZ, 256>>>(b_d, out);
}

// round 6
// speedup vs baseline: 60.4733x; 1.1843x over previous
#include <cuda_runtime.h>
#include <math.h>

// ---------------- problem constants ----------------
#define T_STEPS 64
#define B_SZ    128
#define M_COLS  1000
#define N_CELLS 4
#define TC      4000      // M_COLS * N_CELLS
#define K_TOP   25
#define D_IN    1024
#define D_OUT   1024

// ---------------- persistent device state ----------------
__device__ float g_za_all[T_STEPS * B_SZ * M_COLS]; // pre-computed feedforward drive
__device__ float g_wbt  [TC * TC];                  // w_b transposed
__device__ float g_wdt  [M_COLS * D_OUT];           // w_d transposed
__device__ int   g_ycidx[T_STEPS * B_SZ * K_TOP];   // selected columns per (t,b)
__device__ float g_ycval[T_STEPS * B_SZ * K_TOP];   // max(y,0) per (t,b)

// ---------------- generic 32x32 tiled transpose with bounds ----------------
__global__ void transpose_kernel(const float* __restrict__ in, float* __restrict__ out,
                                 int rows, int cols)
{
    __shared__ float tile[32][33];
    int c0 = blockIdx.x * 32, r0 = blockIdx.y * 32;
#pragma unroll
    for (int j = 0; j < 32; j += 8) {
        int r = r0 + threadIdx.y + j, c = c0 + threadIdx.x;
        if (r < rows && c < cols)
            tile[threadIdx.y + j][threadIdx.x] = in[(size_t)r * cols + c];
    }
    __syncthreads();
#pragma unroll
    for (int j = 0; j < 32; j += 8) {
        int c = c0 + threadIdx.y + j, r = r0 + threadIdx.x;
        if (r < rows && c < cols)
            out[(size_t)c * rows + r] = tile[threadIdx.x][threadIdx.y + j];
    }
}

// ---------------- NT SGEMM with packed f32x2 FMA, double-buffered ----------------
// C[m,n] = sum_k A[m,k]*B[n,k]. BM=128, BN=128, BK=8, TM=8, TN=8, 256 threads.
// Mrows % BM == 0, Kdim % BK == 0; Ncols may be ragged.
template<int BM, int BN, int BK, int TM, int TN>
__global__ void __launch_bounds__(256)
sgemm_nt_f32x2(int Mrows, int Ncols, int Kdim,
               const float* __restrict__ A,
               const float* __restrict__ B,
               float* __restrict__ C)
{
    __shared__ float As[2][BK][BM + 4];
    __shared__ float Bs[2][BK][BN + 8];

    const int tid = threadIdx.x;
    const int tn  = tid % (BN / TN);       // 0..15
    const int tm  = tid / (BN / TN);       // 0..15
    const int m0  = blockIdx.y * BM;
    const int n0  = blockIdx.x * BN;

    // load mapping: each thread loads 1 float4 of A and 1 of B per tile
    const int arow = tid >> 1, aq = tid & 1;   // 128 rows x 2 quads

    // acc packed: acc[i][j2] holds columns (2*j2, 2*j2+1)
    unsigned long long acc[TM][TN / 2];
#pragma unroll
    for (int i = 0; i < TM; i++)
#pragma unroll
        for (int j = 0; j < TN / 2; j++) acc[i][j] = 0ull;

    // prime buffer 0
    float4 aReg = *reinterpret_cast<const float4*>(&A[(size_t)(m0 + arow) * Kdim + aq * 4]);
    float4 bReg = make_float4(0.f, 0.f, 0.f, 0.f);
    if (n0 + arow < Ncols)
        bReg = *reinterpret_cast<const float4*>(&B[(size_t)(n0 + arow) * Kdim + aq * 4]);
    {
        As[0][aq * 4 + 0][arow] = aReg.x; As[0][aq * 4 + 1][arow] = aReg.y;
        As[0][aq * 4 + 2][arow] = aReg.z; As[0][aq * 4 + 3][arow] = aReg.w;
        Bs[0][aq * 4 + 0][arow] = bReg.x; Bs[0][aq * 4 + 1][arow] = bReg.y;
        Bs[0][aq * 4 + 2][arow] = bReg.z; Bs[0][aq * 4 + 3][arow] = bReg.w;
    }
    __syncthreads();

    const int nk = Kdim / BK;
    for (int kt = 0; kt < nk; kt++) {
        const int buf = kt & 1;
        // prefetch next tile into registers
        if (kt + 1 < nk) {
            int kb = (kt + 1) * BK;
            aReg = *reinterpret_cast<const float4*>(&A[(size_t)(m0 + arow) * Kdim + kb + aq * 4]);
            bReg = make_float4(0.f, 0.f, 0.f, 0.f);
            if (n0 + arow < Ncols)
                bReg = *reinterpret_cast<const float4*>(&B[(size_t)(n0 + arow) * Kdim + kb + aq * 4]);
        }

#pragma unroll
        for (int k = 0; k < BK; k++) {
            float4 a0 = *reinterpret_cast<const float4*>(&As[buf][k][tm * TM]);
            float4 a1 = *reinterpret_cast<const float4*>(&As[buf][k][tm * TM + 4]);
            const unsigned long long* bp =
                reinterpret_cast<const unsigned long long*>(&Bs[buf][k][tn * TN]);
            unsigned long long b2[4] = {bp[0], bp[1], bp[2], bp[3]};
            float av[8] = {a0.x, a0.y, a0.z, a0.w, a1.x, a1.y, a1.z, a1.w};
#pragma unroll
            for (int i = 0; i < TM; i++) {
                unsigned int au = __float_as_uint(av[i]);
                unsigned long long ap;
                asm("mov.b64 %0, {%1, %1};" : "=l"(ap) : "r"(au));
#pragma unroll
                for (int j = 0; j < TN / 2; j++)
                    asm("fma.rn.f32x2 %0, %1, %2, %0;" : "+l"(acc[i][j]) : "l"(ap), "l"(b2[j]));
            }
        }

        if (kt + 1 < nk) {
            const int nb = buf ^ 1;
            As[nb][aq * 4 + 0][arow] = aReg.x; As[nb][aq * 4 + 1][arow] = aReg.y;
            As[nb][aq * 4 + 2][arow] = aReg.z; As[nb][aq * 4 + 3][arow] = aReg.w;
            Bs[nb][aq * 4 + 0][arow] = bReg.x; Bs[nb][aq * 4 + 1][arow] = bReg.y;
            Bs[nb][aq * 4 + 2][arow] = bReg.z; Bs[nb][aq * 4 + 3][arow] = bReg.w;
            __syncthreads();
        }
    }

#pragma unroll
    for (int i = 0; i < TM; i++) {
        int gm = m0 + tm * TM + i;
#pragma unroll
        for (int j = 0; j < TN / 2; j++) {
            unsigned int lo, hi;
            asm("mov.b64 {%0, %1}, %2;" : "=r"(lo), "=r"(hi) : "l"(acc[i][j]));
            int gn = n0 + tn * TN + 2 * j;
            if (gn < Ncols)     C[(size_t)gm * Ncols + gn]     = __uint_as_float(lo);
            if (gn + 1 < Ncols) C[(size_t)gm * Ncols + gn + 1] = __uint_as_float(hi);
        }
    }
}

// ---------------- lane-local tree max over 32 register values ----------------
// returns (max value, its j index); ties -> smaller j
__device__ __forceinline__ void tree_max32(const float v[32], float& bv, int& bj)
{
    float tv[16]; int tj[16];
#pragma unroll
    for (int j = 0; j < 16; j++) {
        bool t = v[2 * j + 1] > v[2 * j];
        tv[j] = t ? v[2 * j + 1] : v[2 * j];
        tj[j] = t ? 2 * j + 1 : 2 * j;
    }
#pragma unroll
    for (int s = 8; s >= 1; s >>= 1) {
#pragma unroll
        for (int j = 0; j < s; j++) {
            bool t = tv[j + s] > tv[j];            // strict: keep lower index on tie
            tv[j] = t ? tv[j + s] : tv[j];
            tj[j] = t ? tj[j + s] : tj[j];
        }
    }
    bv = tv[0]; bj = tj[0];
}

// ---------------- persistent scan kernel: one block per batch row ----------------
__global__ void __launch_bounds__(512) rsm_scan_kernel()
{
    const int b      = blockIdx.x;
    const int tid    = threadIdx.x;
    const int lane   = tid & 31;
    const int warpid = tid >> 5;

    __shared__ float         s_psi[TC];        // psi == phi (EPS == GAMMA)
    __shared__ float         s_zb [TC];
    __shared__ float         s_lam[M_COLS];
    __shared__ float         s_sig[M_COLS];
    __shared__ float         s_yw [M_COLS];
    __shared__ unsigned char s_win[M_COLS];
    __shared__ int           s_didx [K_TOP];
    __shared__ float         s_delta[K_TOP];

    for (int i = tid; i < TC; i += 512) { s_psi[i] = 0.f; s_zb[i] = 0.f; }
    __syncthreads();

    for (int t = 0; t < T_STEPS; t++) {
        const float* zab = g_za_all + ((size_t)t * B_SZ + b) * M_COLS;

        // ---- phase A: per-column winner + column max of pi ----
#pragma unroll
        for (int h = 0; h < 2; h++) {
            int c = tid + h * 512;
            if (c < M_COLS) {
                float  zac = zab[c];
                float4 zb  = *reinterpret_cast<const float4*>(&s_zb [c * 4]);
                float4 ph  = *reinterpret_cast<const float4*>(&s_psi[c * 4]);
                float sig[4] = {zac + zb.x, zac + zb.y, zac + zb.z, zac + zb.w};
                float pv [4] = {sig[0] * (1.f - ph.x), sig[1] * (1.f - ph.y),
                                sig[2] * (1.f - ph.z), sig[3] * (1.f - ph.w)};
                float best = pv[0]; int bw = 0;
#pragma unroll
                for (int n = 1; n < N_CELLS; n++)
                    if (pv[n] > best) { best = pv[n]; bw = n; }
                s_lam[c] = best;
                s_win[c] = (unsigned char)bw;
                s_sig[c] = sig[bw];
                s_yw [c] = 0.f;
            }
        }
        __syncthreads();

        // ---- phase T: top-K by warp 0 (value desc, col asc on ties) ----
        if (warpid == 0) {
            float v[32];
#pragma unroll
            for (int j = 0; j < 32; j++) {
                int c = j * 32 + lane;
                v[j] = (c < M_COLS) ? s_lam[c] : -INFINITY;
            }
            float lv; int lj;
            tree_max32(v, lv, lj);
            int mycol = 0;

            for (int it = 0; it < K_TOP; it++) {
                float bv = lv;
                int   bc = lj * 32 + lane;
#pragma unroll
                for (int off = 16; off > 0; off >>= 1) {
                    float ov = __shfl_xor_sync(0xffffffffu, bv, off);
                    int   oc = __shfl_xor_sync(0xffffffffu, bc, off);
                    if (ov > bv || (ov == bv && oc < bc)) { bv = ov; bc = oc; }
                }
                if (lane == it) mycol = bc;            // winner kept in register
                if ((bc & 31) == lane) {               // owning lane removes & rescans
                    v[bc >> 5] = -INFINITY;
                    tree_max32(v, lv, lj);
                }
            }
            __syncwarp();

            // ---- emit: lanes 0..24 handle one winner each ----
            if (lane < K_TOP) {
                int   c    = mycol;
                int   w    = (int)s_win[c];
                int   cell = c * N_CELLS + w;
                float y    = tanhf(s_sig[c]);
                s_didx [lane] = cell;
                s_delta[lane] = fmaxf(y - 0.5f * s_psi[cell], 0.f);
                s_yw[c] = y;
                size_t o = ((size_t)t * B_SZ + b) * K_TOP + lane;
                g_ycidx[o] = c;
                g_ycval[o] = fmaxf(y, 0.f);
            }
        }
        __syncthreads();

        if (t == T_STEPS - 1) break;

        // ---- phase B: rank-25 z_b update + psi decay/winner-max ----
        {
            const int c0 = tid;              // always < 1000
            const int c1 = tid + 512;
            const bool two = (c1 < M_COLS);

            float4 z0 = *reinterpret_cast<const float4*>(&s_zb[c0 * 4]);
            float4 a0 = make_float4(0.5f * z0.x, 0.5f * z0.y, 0.5f * z0.z, 0.5f * z0.w);
            float4 a1 = make_float4(0.f, 0.f, 0.f, 0.f);
            if (two) {
                float4 z1 = *reinterpret_cast<const float4*>(&s_zb[c1 * 4]);
                a1 = make_float4(0.5f * z1.x, 0.5f * z1.y, 0.5f * z1.z, 0.5f * z1.w);
            }
#pragma unroll
            for (int i = 0; i < K_TOP; i++) {
                float d = s_delta[i];
                const float* base = &g_wbt[(size_t)s_didx[i] * TC];
                float4 w0 = *reinterpret_cast<const float4*>(&base[c0 * 4]);
                a0.x = fmaf(d, w0.x, a0.x); a0.y = fmaf(d, w0.y, a0.y);
                a0.z = fmaf(d, w0.z, a0.z); a0.w = fmaf(d, w0.w, a0.w);
                if (two) {
                    float4 w1 = *reinterpret_cast<const float4*>(&base[c1 * 4]);
                    a1.x = fmaf(d, w1.x, a1.x); a1.y = fmaf(d, w1.y, a1.y);
                    a1.z = fmaf(d, w1.z, a1.z); a1.w = fmaf(d, w1.w, a1.w);
                }
            }
            *reinterpret_cast<float4*>(&s_zb[c0 * 4]) = a0;
            if (two) *reinterpret_cast<float4*>(&s_zb[c1 * 4]) = a1;

#pragma unroll
            for (int h = 0; h < 2; h++) {
                int c = tid + h * 512;
                if (c >= M_COLS) break;
                float4 p = *reinterpret_cast<const float4*>(&s_psi[c * 4]);
                p.x *= 0.5f; p.y *= 0.5f; p.z *= 0.5f; p.w *= 0.5f;
                float y = s_yw[c];
                if (y > 0.f) {
                    int w = (int)s_win[c];
                    if      (w == 0) p.x = fmaxf(p.x, y);
                    else if (w == 1) p.y = fmaxf(p.y, y);
                    else if (w == 2) p.z = fmaxf(p.z, y);
                    else             p.w = fmaxf(p.w, y);
                }
                *reinterpret_cast<float4*>(&s_psi[c * 4]) = p;
            }
        }
        __syncthreads();
    }
}

// ---------------- sparse decode: out[tb] = b_d + sum_i y_i * w_dT[c_i] ----------
__global__ void __launch_bounds__(256) decode_kernel(const float* __restrict__ b_d,
                                                     float* __restrict__ out)
{
    const int tb  = blockIdx.x;
    const int tid = threadIdx.x;

    __shared__ int   s_c[K_TOP];
    __shared__ float s_y[K_TOP];
    if (tid < K_TOP) {
        s_c[tid] = g_ycidx[(size_t)tb * K_TOP + tid];
        s_y[tid] = g_ycval[(size_t)tb * K_TOP + tid];
    }
    __syncthreads();

    float4 acc = *reinterpret_cast<const float4*>(&b_d[tid * 4]);
#pragma unroll
    for (int i = 0; i < K_TOP; i++) {
        float y = s_y[i];
        const float4 w = *reinterpret_cast<const float4*>(
            &g_wdt[(size_t)s_c[i] * D_OUT + tid * 4]);
        acc.x = fmaf(y, w.x, acc.x);
        acc.y = fmaf(y, w.y, acc.y);
        acc.z = fmaf(y, w.z, acc.z);
        acc.w = fmaf(y, w.w, acc.w);
    }
    *reinterpret_cast<float4*>(&out[(size_t)tb * D_OUT + tid * 4]) = acc;
}

// ---------------- host launch ----------------
extern "C" void kernel_launch(void* const* d_in, const int* in_sizes, int n_in,
                              void* d_out, int out_size)
{
    const float* x   = (const float*)d_in[0];   // [T, B, D_IN]
    const float* w_a = (const float*)d_in[1];   // [M, D_IN]
    const float* w_b = (const float*)d_in[2];   // [TC, TC]
    const float* w_d = (const float*)d_in[3];   // [D_OUT, M]
    const float* b_d = (const float*)d_in[4];   // [D_OUT]
    float* out = (float*)d_out;                 // [T, B, D_OUT]

    float *za, *wbt, *wdt;
    cudaGetSymbolAddress((void**)&za,  g_za_all);
    cudaGetSymbolAddress((void**)&wbt, g_wbt);
    cudaGetSymbolAddress((void**)&wdt, g_wdt);

    // transpose w_b (4000x4000) and w_d (1024x1000)
    transpose_kernel<<<dim3(TC / 32, TC / 32), dim3(32, 8)>>>(w_b, wbt, TC, TC);
    transpose_kernel<<<dim3((M_COLS + 31) / 32, D_OUT / 32), dim3(32, 8)>>>(
        w_d, wdt, D_OUT, M_COLS);

    // Pre-compute z_a for ALL timesteps: [8192,1000] = [8192,1024] @ [1000,1024]^T
    {
        constexpr int BM = 128, BN = 128, BK = 8, TM = 8, TN = 8;
        dim3 grid((M_COLS + BN - 1) / BN, (T_STEPS * B_SZ) / BM);   // 8 x 64
        sgemm_nt_f32x2<BM, BN, BK, TM, TN><<<grid, 256>>>(
            T_STEPS * B_SZ, M_COLS, D_IN, x, w_a, za);
    }

    // Entire 64-step scan in ONE persistent kernel (one block per batch row)
    rsm_scan_kernel<<<B_SZ, 512>>>();

    // Sparse decode for all timesteps
    decode_kernel<<<T_STEPS * B_SZ, 256>>>(b_d, out);
}

// round 7
// speedup vs baseline: 69.8991x; 1.1559x over previous
#include <cuda_runtime.h>
#include <math.h>

// ---------------- problem constants ----------------
#define T_STEPS 64
#define B_SZ    128
#define M_COLS  1000
#define N_CELLS 4
#define TC      4000      // M_COLS * N_CELLS
#define K_TOP   25
#define D_IN    1024
#define D_OUT   1024

// ---------------- persistent device state ----------------
__device__ float g_za_all[T_STEPS * B_SZ * M_COLS]; // pre-computed feedforward drive
__device__ float g_wbt  [TC * TC];                  // w_b transposed
__device__ float g_wdt  [M_COLS * D_OUT];           // w_d transposed
__device__ int   g_ycidx[T_STEPS * B_SZ * K_TOP];   // selected columns per (t,b)
__device__ float g_ycval[T_STEPS * B_SZ * K_TOP];   // max(y,0) per (t,b)

// ---------------- generic 32x32 tiled transpose with bounds ----------------
__global__ void transpose_kernel(const float* __restrict__ in, float* __restrict__ out,
                                 int rows, int cols)
{
    __shared__ float tile[32][33];
    int c0 = blockIdx.x * 32, r0 = blockIdx.y * 32;
#pragma unroll
    for (int j = 0; j < 32; j += 8) {
        int r = r0 + threadIdx.y + j, c = c0 + threadIdx.x;
        if (r < rows && c < cols)
            tile[threadIdx.y + j][threadIdx.x] = in[(size_t)r * cols + c];
    }
    __syncthreads();
#pragma unroll
    for (int j = 0; j < 32; j += 8) {
        int c = c0 + threadIdx.y + j, r = r0 + threadIdx.x;
        if (r < rows && c < cols)
            out[(size_t)c * rows + r] = tile[threadIdx.x][threadIdx.y + j];
    }
}

// ---------------- NT SGEMM with packed f32x2 FMA, double-buffered ----------------
template<int BM, int BN, int BK, int TM, int TN>
__global__ void __launch_bounds__(256)
sgemm_nt_f32x2(int Mrows, int Ncols, int Kdim,
               const float* __restrict__ A,
               const float* __restrict__ B,
               float* __restrict__ C)
{
    __shared__ float As[2][BK][BM + 4];
    __shared__ float Bs[2][BK][BN + 8];

    const int tid = threadIdx.x;
    const int tn  = tid % (BN / TN);
    const int tm  = tid / (BN / TN);
    const int m0  = blockIdx.y * BM;
    const int n0  = blockIdx.x * BN;

    const int arow = tid >> 1, aq = tid & 1;

    unsigned long long acc[TM][TN / 2];
#pragma unroll
    for (int i = 0; i < TM; i++)
#pragma unroll
        for (int j = 0; j < TN / 2; j++) acc[i][j] = 0ull;

    float4 aReg = *reinterpret_cast<const float4*>(&A[(size_t)(m0 + arow) * Kdim + aq * 4]);
    float4 bReg = make_float4(0.f, 0.f, 0.f, 0.f);
    if (n0 + arow < Ncols)
        bReg = *reinterpret_cast<const float4*>(&B[(size_t)(n0 + arow) * Kdim + aq * 4]);
    {
        As[0][aq * 4 + 0][arow] = aReg.x; As[0][aq * 4 + 1][arow] = aReg.y;
        As[0][aq * 4 + 2][arow] = aReg.z; As[0][aq * 4 + 3][arow] = aReg.w;
        Bs[0][aq * 4 + 0][arow] = bReg.x; Bs[0][aq * 4 + 1][arow] = bReg.y;
        Bs[0][aq * 4 + 2][arow] = bReg.z; Bs[0][aq * 4 + 3][arow] = bReg.w;
    }
    __syncthreads();

    const int nk = Kdim / BK;
    for (int kt = 0; kt < nk; kt++) {
        const int buf = kt & 1;
        if (kt + 1 < nk) {
            int kb = (kt + 1) * BK;
            aReg = *reinterpret_cast<const float4*>(&A[(size_t)(m0 + arow) * Kdim + kb + aq * 4]);
            bReg = make_float4(0.f, 0.f, 0.f, 0.f);
            if (n0 + arow < Ncols)
                bReg = *reinterpret_cast<const float4*>(&B[(size_t)(n0 + arow) * Kdim + kb + aq * 4]);
        }

#pragma unroll
        for (int k = 0; k < BK; k++) {
            float4 a0 = *reinterpret_cast<const float4*>(&As[buf][k][tm * TM]);
            float4 a1 = *reinterpret_cast<const float4*>(&As[buf][k][tm * TM + 4]);
            const unsigned long long* bp =
                reinterpret_cast<const unsigned long long*>(&Bs[buf][k][tn * TN]);
            unsigned long long b2[4] = {bp[0], bp[1], bp[2], bp[3]};
            float av[8] = {a0.x, a0.y, a0.z, a0.w, a1.x, a1.y, a1.z, a1.w};
#pragma unroll
            for (int i = 0; i < TM; i++) {
                unsigned int au = __float_as_uint(av[i]);
                unsigned long long ap;
                asm("mov.b64 %0, {%1, %1};" : "=l"(ap) : "r"(au));
#pragma unroll
                for (int j = 0; j < TN / 2; j++)
                    asm("fma.rn.f32x2 %0, %1, %2, %0;" : "+l"(acc[i][j]) : "l"(ap), "l"(b2[j]));
            }
        }

        if (kt + 1 < nk) {
            const int nb = buf ^ 1;
            As[nb][aq * 4 + 0][arow] = aReg.x; As[nb][aq * 4 + 1][arow] = aReg.y;
            As[nb][aq * 4 + 2][arow] = aReg.z; As[nb][aq * 4 + 3][arow] = aReg.w;
            Bs[nb][aq * 4 + 0][arow] = bReg.x; Bs[nb][aq * 4 + 1][arow] = bReg.y;
            Bs[nb][aq * 4 + 2][arow] = bReg.z; Bs[nb][aq * 4 + 3][arow] = bReg.w;
            __syncthreads();
        }
    }

#pragma unroll
    for (int i = 0; i < TM; i++) {
        int gm = m0 + tm * TM + i;
#pragma unroll
        for (int j = 0; j < TN / 2; j++) {
            unsigned int lo, hi;
            asm("mov.b64 {%0, %1}, %2;" : "=r"(lo), "=r"(hi) : "l"(acc[i][j]));
            int gn = n0 + tn * TN + 2 * j;
            if (gn < Ncols)     C[(size_t)gm * Ncols + gn]     = __uint_as_float(lo);
            if (gn + 1 < Ncols) C[(size_t)gm * Ncols + gn + 1] = __uint_as_float(hi);
        }
    }
}

// ---------------- helpers ----------------
// order-preserving float -> uint mapping (exact: a > b  <=>  ord(a) > ord(b))
__device__ __forceinline__ unsigned int ord_key(float f) {
    unsigned int u = __float_as_uint(f);
    return (u & 0x80000000u) ? ~u : (u | 0x80000000u);
}

// lane-local tree max over 32 register values; ties -> smaller j
__device__ __forceinline__ void tree_max32(const float v[32], float& bv, int& bj)
{
    float tv[16]; int tj[16];
#pragma unroll
    for (int j = 0; j < 16; j++) {
        bool t = v[2 * j + 1] > v[2 * j];
        tv[j] = t ? v[2 * j + 1] : v[2 * j];
        tj[j] = t ? 2 * j + 1 : 2 * j;
    }
#pragma unroll
    for (int s = 8; s >= 1; s >>= 1) {
#pragma unroll
        for (int j = 0; j < s; j++) {
            bool t = tv[j + s] > tv[j];
            tv[j] = t ? tv[j + s] : tv[j];
            tj[j] = t ? tj[j + s] : tj[j];
        }
    }
    bv = tv[0]; bj = tj[0];
}

// ---------------- persistent scan kernel: one block per batch row ----------------
__global__ void __launch_bounds__(512) rsm_scan_kernel()
{
    const int b      = blockIdx.x;
    const int tid    = threadIdx.x;
    const int lane   = tid & 31;
    const int warpid = tid >> 5;

    __shared__ float         s_psi[TC];        // psi == phi (EPS == GAMMA)
    __shared__ float         s_zb [TC];
    __shared__ float         s_lam[M_COLS];
    __shared__ float         s_sig[M_COLS];
    __shared__ unsigned char s_win[M_COLS];
    __shared__ int           s_didx [K_TOP];
    __shared__ float         s_delta[K_TOP];

    for (int i = tid; i < TC; i += 512) { s_psi[i] = 0.f; s_zb[i] = 0.f; }
    __syncthreads();

    for (int t = 0; t < T_STEPS; t++) {
        const float* zab = g_za_all + ((size_t)t * B_SZ + b) * M_COLS;

        // ---- phase A: winner cell + column max of pi + psi decay (fused) ----
#pragma unroll
        for (int h = 0; h < 2; h++) {
            int c = tid + h * 512;
            if (c < M_COLS) {
                float  zac = __ldg(&zab[c]);
                float4 zb  = *reinterpret_cast<const float4*>(&s_zb [c * 4]);
                float4 ph  = *reinterpret_cast<const float4*>(&s_psi[c * 4]);
                float sig[4] = {zac + zb.x, zac + zb.y, zac + zb.z, zac + zb.w};
                float pv [4] = {sig[0] * (1.f - ph.x), sig[1] * (1.f - ph.y),
                                sig[2] * (1.f - ph.z), sig[3] * (1.f - ph.w)};
                float best = pv[0]; int bw = 0;
#pragma unroll
                for (int n = 1; n < N_CELLS; n++)
                    if (pv[n] > best) { best = pv[n]; bw = n; }
                s_lam[c] = best;
                s_win[c] = (unsigned char)bw;
                s_sig[c] = sig[bw];
                // decay psi in place (winner cells fixed up by emit below)
                *reinterpret_cast<float4*>(&s_psi[c * 4]) =
                    make_float4(0.5f * ph.x, 0.5f * ph.y, 0.5f * ph.z, 0.5f * ph.w);
            }
        }
        __syncthreads();

        // ---- phase T: top-K by warp 0 via REDUX (value desc, col asc on ties) ----
        if (warpid == 0) {
            float v[32];
#pragma unroll
            for (int j = 0; j < 32; j++) {
                int c = j * 32 + lane;
                v[j] = (c < M_COLS) ? s_lam[c] : -INFINITY;
            }
            float lv; int lj;
            tree_max32(v, lv, lj);
            int mycol = 0;

            for (int it = 0; it < K_TOP; it++) {
                unsigned int key = ord_key(lv);
                unsigned int m   = __reduce_max_sync(0xffffffffu, key);
                unsigned int cand = (key == m) ? (unsigned int)(lj * 32 + lane)
                                               : 0xffffffffu;
                unsigned int c = __reduce_min_sync(0xffffffffu, cand);
                if (lane == it) mycol = (int)c;
                if (((int)c & 31) == lane) {        // owning lane removes & rescans
                    v[(int)c >> 5] = -INFINITY;
                    tree_max32(v, lv, lj);
                }
            }
            __syncwarp();

            // ---- emit: lanes 0..24, one winner each (psi already decayed) ----
            if (lane < K_TOP) {
                int   c    = mycol;
                int   w    = (int)s_win[c];
                int   cell = c * N_CELLS + w;
                float y    = tanhf(s_sig[c]);
                float pd   = s_psi[cell];                 // decayed psi
                s_didx [lane] = cell;
                s_delta[lane] = fmaxf(y - pd, 0.f);
                s_psi[cell]   = fmaxf(pd, y);
                size_t o = ((size_t)t * B_SZ + b) * K_TOP + lane;
                g_ycidx[o] = c;
                g_ycval[o] = fmaxf(y, 0.f);
            }
        }
        __syncthreads();

        if (t == T_STEPS - 1) break;

        // ---- phase B: pure rank-25 z_b update ----
        {
            const int c0 = tid;
            const int c1 = tid + 512;
            const bool two = (c1 < M_COLS);

            float4 z0 = *reinterpret_cast<const float4*>(&s_zb[c0 * 4]);
            float4 a0 = make_float4(0.5f * z0.x, 0.5f * z0.y, 0.5f * z0.z, 0.5f * z0.w);
            float4 a1 = make_float4(0.f, 0.f, 0.f, 0.f);
            if (two) {
                float4 z1 = *reinterpret_cast<const float4*>(&s_zb[c1 * 4]);
                a1 = make_float4(0.5f * z1.x, 0.5f * z1.y, 0.5f * z1.z, 0.5f * z1.w);
            }
#pragma unroll
            for (int i = 0; i < K_TOP; i++) {
                float d = s_delta[i];
                const float* base = &g_wbt[(size_t)s_didx[i] * TC];
                float4 w0 = *reinterpret_cast<const float4*>(&base[c0 * 4]);
                a0.x = fmaf(d, w0.x, a0.x); a0.y = fmaf(d, w0.y, a0.y);
                a0.z = fmaf(d, w0.z, a0.z); a0.w = fmaf(d, w0.w, a0.w);
                if (two) {
                    float4 w1 = *reinterpret_cast<const float4*>(&base[c1 * 4]);
                    a1.x = fmaf(d, w1.x, a1.x); a1.y = fmaf(d, w1.y, a1.y);
                    a1.z = fmaf(d, w1.z, a1.z); a1.w = fmaf(d, w1.w, a1.w);
                }
            }
            *reinterpret_cast<float4*>(&s_zb[c0 * 4]) = a0;
            if (two) *reinterpret_cast<float4*>(&s_zb[c1 * 4]) = a1;
        }
        __syncthreads();
    }
}

// ---------------- sparse decode: out[tb] = b_d + sum_i y_i * w_dT[c_i] ----------
__global__ void __launch_bounds__(256) decode_kernel(const float* __restrict__ b_d,
                                                     float* __restrict__ out)
{
    const int tb  = blockIdx.x;
    const int tid = threadIdx.x;

    __shared__ int   s_c[K_TOP];
    __shared__ float s_y[K_TOP];
    if (tid < K_TOP) {
        s_c[tid] = g_ycidx[(size_t)tb * K_TOP + tid];
        s_y[tid] = g_ycval[(size_t)tb * K_TOP + tid];
    }
    __syncthreads();

    float4 acc = *reinterpret_cast<const float4*>(&b_d[tid * 4]);
#pragma unroll
    for (int i = 0; i < K_TOP; i++) {
        float y = s_y[i];
        const float4 w = *reinterpret_cast<const float4*>(
            &g_wdt[(size_t)s_c[i] * D_OUT + tid * 4]);
        acc.x = fmaf(y, w.x, acc.x);
        acc.y = fmaf(y, w.y, acc.y);
        acc.z = fmaf(y, w.z, acc.z);
        acc.w = fmaf(y, w.w, acc.w);
    }
    *reinterpret_cast<float4*>(&out[(size_t)tb * D_OUT + tid * 4]) = acc;
}

// ---------------- host launch ----------------
extern "C" void kernel_launch(void* const* d_in, const int* in_sizes, int n_in,
                              void* d_out, int out_size)
{
    const float* x   = (const float*)d_in[0];   // [T, B, D_IN]
    const float* w_a = (const float*)d_in[1];   // [M, D_IN]
    const float* w_b = (const float*)d_in[2];   // [TC, TC]
    const float* w_d = (const float*)d_in[3];   // [D_OUT, M]
    const float* b_d = (const float*)d_in[4];   // [D_OUT]
    float* out = (float*)d_out;                 // [T, B, D_OUT]

    float *za, *wbt, *wdt;
    cudaGetSymbolAddress((void**)&za,  g_za_all);
    cudaGetSymbolAddress((void**)&wbt, g_wbt);
    cudaGetSymbolAddress((void**)&wdt, g_wdt);

    // transpose w_b (4000x4000) and w_d (1024x1000)
    transpose_kernel<<<dim3(TC / 32, TC / 32), dim3(32, 8)>>>(w_b, wbt, TC, TC);
    transpose_kernel<<<dim3((M_COLS + 31) / 32, D_OUT / 32), dim3(32, 8)>>>(
        w_d, wdt, D_OUT, M_COLS);

    // Pre-compute z_a for ALL timesteps: [8192,1000] = [8192,1024] @ [1000,1024]^T
    {
        constexpr int BM = 128, BN = 128, BK = 8, TM = 8, TN = 8;
        dim3 grid((M_COLS + BN - 1) / BN, (T_STEPS * B_SZ) / BM);   // 8 x 64
        sgemm_nt_f32x2<BM, BN, BK, TM, TN><<<grid, 256>>>(
            T_STEPS * B_SZ, M_COLS, D_IN, x, w_a, za);
    }

    // Entire 64-step scan in ONE persistent kernel (one block per batch row)
    rsm_scan_kernel<<<B_SZ, 512>>>();

    // Sparse decode for all timesteps
    decode_kernel<<<T_STEPS * B_SZ, 256>>>(b_d, out);
}

// round 8
// speedup vs baseline: 79.2637x; 1.1340x over previous
#include <cuda_runtime.h>
#include <math.h>

// ---------------- problem constants ----------------
#define T_STEPS 64
#define B_SZ    128
#define M_COLS  1000
#define N_CELLS 4
#define TC      4000      // M_COLS * N_CELLS
#define K_TOP   25
#define D_IN    1024
#define D_OUT   1024
#define GEMM_BLOCKS 512   // 64 timesteps x 8 column tiles

// ---------------- persistent device state ----------------
__device__ float g_za_all[T_STEPS * B_SZ * M_COLS]; // feedforward drive
__device__ float g_wbt  [TC * TC];                  // w_b transposed
__device__ float g_wdt  [M_COLS * D_OUT];           // w_d transposed
__device__ int   g_ycidx[T_STEPS * B_SZ * K_TOP];   // selected columns per (t,b)
__device__ float g_ycval[T_STEPS * B_SZ * K_TOP];   // max(y,0) per (t,b)
__device__ int   g_cnt  [T_STEPS];                  // za readiness counters

// ---------------- init (counters must reset every graph replay) ----------------
__global__ void zero_cnt_kernel() {
    if (threadIdx.x < T_STEPS) g_cnt[threadIdx.x] = 0;
}

// ---------------- generic 32x32 tiled transpose with bounds ----------------
__global__ void transpose_kernel(const float* __restrict__ in, float* __restrict__ out,
                                 int rows, int cols)
{
    __shared__ float tile[32][33];
    int c0 = blockIdx.x * 32, r0 = blockIdx.y * 32;
#pragma unroll
    for (int j = 0; j < 32; j += 8) {
        int r = r0 + threadIdx.y + j, c = c0 + threadIdx.x;
        if (r < rows && c < cols)
            tile[threadIdx.y + j][threadIdx.x] = in[(size_t)r * cols + c];
    }
    __syncthreads();
#pragma unroll
    for (int j = 0; j < 32; j += 8) {
        int c = c0 + threadIdx.y + j, r = r0 + threadIdx.x;
        if (r < rows && c < cols)
            out[(size_t)c * rows + r] = tile[threadIdx.x][threadIdx.y + j];
    }
}

// ---------------- helpers ----------------
__device__ __forceinline__ unsigned int ord_key(float f) {
    unsigned int u = __float_as_uint(f);
    return (u & 0x80000000u) ? ~u : (u | 0x80000000u);
}

__device__ __forceinline__ void tree_max32(const float v[32], float& bv, int& bj)
{
    float tv[16]; int tj[16];
#pragma unroll
    for (int j = 0; j < 16; j++) {
        bool t = v[2 * j + 1] > v[2 * j];
        tv[j] = t ? v[2 * j + 1] : v[2 * j];
        tj[j] = t ? 2 * j + 1 : 2 * j;
    }
#pragma unroll
    for (int s = 8; s >= 1; s >>= 1) {
#pragma unroll
        for (int j = 0; j < s; j++) {
            bool t = tv[j + s] > tv[j];
            tv[j] = t ? tv[j + s] : tv[j];
            tj[j] = t ? tj[j + s] : tj[j];
        }
    }
    bv = tv[0]; bj = tj[0];
}

// ---------------- shared memory overlays ----------------
struct GemmSmem {                       // 34,304 B
    float As[2][16][128 + 4];
    float Bs[2][16][128 + 8];
};
struct ScanSmem {                       // ~25.3 KB
    float         psi[TC];
    float         lam[M_COLS];
    float         sig[M_COLS];
    unsigned char win[M_COLS];
    int           didx [K_TOP];
    float         delta[K_TOP];
};

// ---------------- GEMM part: one 128x128 za tile, then signal ----------------
__device__ void gemm_part(const float* __restrict__ x, const float* __restrict__ w_a,
                          char* smem)
{
    GemmSmem* S = reinterpret_cast<GemmSmem*>(smem);
    const int bid = blockIdx.x;
    const int t   = bid >> 3;
    const int n0  = (bid & 7) * 128;
    const int tid = threadIdx.x;
    const int tn  = tid & 31;          // column group (tn*4)
    const int tm  = tid >> 5;          // row group (tm*8)
    const int arow = tid >> 2, aq = tid & 3;

    const float* A = x + (size_t)t * B_SZ * D_IN;      // [128,1024]
    float*       C = g_za_all + (size_t)t * B_SZ * M_COLS;

    unsigned long long acc[8][2];
#pragma unroll
    for (int i = 0; i < 8; i++) { acc[i][0] = 0ull; acc[i][1] = 0ull; }

    float4 aR = *reinterpret_cast<const float4*>(&A[(size_t)arow * D_IN + aq * 4]);
    float4 bR = make_float4(0.f, 0.f, 0.f, 0.f);
    if (n0 + arow < M_COLS)
        bR = *reinterpret_cast<const float4*>(&w_a[(size_t)(n0 + arow) * D_IN + aq * 4]);
    {
        S->As[0][aq * 4 + 0][arow] = aR.x; S->As[0][aq * 4 + 1][arow] = aR.y;
        S->As[0][aq * 4 + 2][arow] = aR.z; S->As[0][aq * 4 + 3][arow] = aR.w;
        S->Bs[0][aq * 4 + 0][arow] = bR.x; S->Bs[0][aq * 4 + 1][arow] = bR.y;
        S->Bs[0][aq * 4 + 2][arow] = bR.z; S->Bs[0][aq * 4 + 3][arow] = bR.w;
    }
    __syncthreads();

    const int nk = D_IN / 16;                          // 64
    for (int kt = 0; kt < nk; kt++) {
        const int buf = kt & 1;
        if (kt + 1 < nk) {
            int kb = (kt + 1) * 16;
            aR = *reinterpret_cast<const float4*>(&A[(size_t)arow * D_IN + kb + aq * 4]);
            bR = make_float4(0.f, 0.f, 0.f, 0.f);
            if (n0 + arow < M_COLS)
                bR = *reinterpret_cast<const float4*>(&w_a[(size_t)(n0 + arow) * D_IN + kb + aq * 4]);
        }
#pragma unroll
        for (int k = 0; k < 16; k++) {
            float4 a0 = *reinterpret_cast<const float4*>(&S->As[buf][k][tm * 8]);
            float4 a1 = *reinterpret_cast<const float4*>(&S->As[buf][k][tm * 8 + 4]);
            const unsigned long long* bp =
                reinterpret_cast<const unsigned long long*>(&S->Bs[buf][k][tn * 4]);
            unsigned long long b2[2] = {bp[0], bp[1]};
            float av[8] = {a0.x, a0.y, a0.z, a0.w, a1.x, a1.y, a1.z, a1.w};
#pragma unroll
            for (int i = 0; i < 8; i++) {
                unsigned int au = __float_as_uint(av[i]);
                unsigned long long ap;
                asm("mov.b64 %0, {%1, %1};" : "=l"(ap) : "r"(au));
                asm("fma.rn.f32x2 %0, %1, %2, %0;" : "+l"(acc[i][0]) : "l"(ap), "l"(b2[0]));
                asm("fma.rn.f32x2 %0, %1, %2, %0;" : "+l"(acc[i][1]) : "l"(ap), "l"(b2[1]));
            }
        }
        if (kt + 1 < nk) {
            const int nb = buf ^ 1;
            S->As[nb][aq * 4 + 0][arow] = aR.x; S->As[nb][aq * 4 + 1][arow] = aR.y;
            S->As[nb][aq * 4 + 2][arow] = aR.z; S->As[nb][aq * 4 + 3][arow] = aR.w;
            S->Bs[nb][aq * 4 + 0][arow] = bR.x; S->Bs[nb][aq * 4 + 1][arow] = bR.y;
            S->Bs[nb][aq * 4 + 2][arow] = bR.z; S->Bs[nb][aq * 4 + 3][arow] = bR.w;
            __syncthreads();
        }
    }

#pragma unroll
    for (int i = 0; i < 8; i++) {
        int gm = tm * 8 + i;
#pragma unroll
        for (int j = 0; j < 2; j++) {
            unsigned int lo, hi;
            asm("mov.b64 {%0, %1}, %2;" : "=r"(lo), "=r"(hi) : "l"(acc[i][j]));
            int gn = n0 + tn * 4 + 2 * j;
            if (gn < M_COLS)     C[(size_t)gm * M_COLS + gn]     = __uint_as_float(lo);
            if (gn + 1 < M_COLS) C[(size_t)gm * M_COLS + gn + 1] = __uint_as_float(hi);
        }
    }

    // signal: tile ready
    __threadfence();
    __syncthreads();
    if (threadIdx.x == 0) atomicAdd(&g_cnt[t], 1);
}

// ---------------- scan part: one block per batch row, z_b in registers ----------
__device__ void scan_part(char* smem)
{
    ScanSmem* S = reinterpret_cast<ScanSmem*>(smem);
    const int b      = blockIdx.x - GEMM_BLOCKS;
    const int tid    = threadIdx.x;
    const int lane   = tid & 31;
    const int warpid = tid >> 5;

    const int c0 = tid;                // column 0..511
    const int c1 = tid + 512;          // column 512..1023 (valid < 1000)
    const bool two = (c1 < M_COLS);

    for (int i = tid; i < TC; i += 512) S->psi[i] = 0.f;
    float4 z0 = make_float4(0.f, 0.f, 0.f, 0.f);
    float4 z1 = make_float4(0.f, 0.f, 0.f, 0.f);
    __syncthreads();

    for (int t = 0; t < T_STEPS; t++) {
        // wait for za[t] (8 tiles)
        if (tid == 0) {
            unsigned int v;
            do {
                asm volatile("ld.acquire.gpu.u32 %0, [%1];"
                             : "=r"(v) : "l"(&g_cnt[t]) : "memory");
            } while (v < 8u);
        }
        __syncthreads();

        // ---- fused: rank-25 z_b update (t>0) + winner/lam + psi decay ----
        if (t > 0) {
            float4 a0 = make_float4(0.5f * z0.x, 0.5f * z0.y, 0.5f * z0.z, 0.5f * z0.w);
            float4 a1 = make_float4(0.5f * z1.x, 0.5f * z1.y, 0.5f * z1.z, 0.5f * z1.w);
#pragma unroll
            for (int i = 0; i < K_TOP; i++) {
                float d = S->delta[i];
                const float* base = &g_wbt[(size_t)S->didx[i] * TC];
                float4 w0 = *reinterpret_cast<const float4*>(&base[c0 * 4]);
                a0.x = fmaf(d, w0.x, a0.x); a0.y = fmaf(d, w0.y, a0.y);
                a0.z = fmaf(d, w0.z, a0.z); a0.w = fmaf(d, w0.w, a0.w);
                if (two) {
                    float4 w1 = *reinterpret_cast<const float4*>(&base[c1 * 4]);
                    a1.x = fmaf(d, w1.x, a1.x); a1.y = fmaf(d, w1.y, a1.y);
                    a1.z = fmaf(d, w1.z, a1.z); a1.w = fmaf(d, w1.w, a1.w);
                }
            }
            z0 = a0; z1 = a1;
        }

        const float* zab = g_za_all + ((size_t)t * B_SZ + b) * M_COLS;
#pragma unroll
        for (int h = 0; h < 2; h++) {
            int c = (h == 0) ? c0 : c1;
            if (h == 1 && !two) break;
            float4 z = (h == 0) ? z0 : z1;
            float  zac = __ldcg(&zab[c]);
            float4 ph  = *reinterpret_cast<const float4*>(&S->psi[c * 4]);
            float sig[4] = {zac + z.x, zac + z.y, zac + z.z, zac + z.w};
            float pv [4] = {sig[0] * (1.f - ph.x), sig[1] * (1.f - ph.y),
                            sig[2] * (1.f - ph.z), sig[3] * (1.f - ph.w)};
            float best = pv[0]; int bw = 0;
#pragma unroll
            for (int n = 1; n < N_CELLS; n++)
                if (pv[n] > best) { best = pv[n]; bw = n; }
            S->lam[c] = best;
            S->win[c] = (unsigned char)bw;
            S->sig[c] = sig[bw];
            *reinterpret_cast<float4*>(&S->psi[c * 4]) =
                make_float4(0.5f * ph.x, 0.5f * ph.y, 0.5f * ph.z, 0.5f * ph.w);
        }
        __syncthreads();

        // ---- top-K by warp 0 via REDUX (value desc, col asc on ties) ----
        if (warpid == 0) {
            float v[32];
#pragma unroll
            for (int j = 0; j < 32; j++) {
                int c = j * 32 + lane;
                v[j] = (c < M_COLS) ? S->lam[c] : -INFINITY;
            }
            float lv; int lj;
            tree_max32(v, lv, lj);
            int mycol = 0;

            for (int it = 0; it < K_TOP; it++) {
                unsigned int key = ord_key(lv);
                unsigned int m   = __reduce_max_sync(0xffffffffu, key);
                unsigned int cand = (key == m) ? (unsigned int)(lj * 32 + lane)
                                               : 0xffffffffu;
                unsigned int c = __reduce_min_sync(0xffffffffu, cand);
                if (lane == it) mycol = (int)c;
                if (((int)c & 31) == lane) {
                    v[(int)c >> 5] = -INFINITY;
                    tree_max32(v, lv, lj);
                }
            }
            __syncwarp();

            if (lane < K_TOP) {
                int   c    = mycol;
                int   w    = (int)S->win[c];
                int   cell = c * N_CELLS + w;
                float y    = tanhf(S->sig[c]);
                float pd   = S->psi[cell];
                S->didx [lane] = cell;
                S->delta[lane] = fmaxf(y - pd, 0.f);
                S->psi[cell]   = fmaxf(pd, y);
                size_t o = ((size_t)t * B_SZ + b) * K_TOP + lane;
                g_ycidx[o] = c;
                g_ycval[o] = fmaxf(y, 0.f);
            }
        }
        __syncthreads();
    }
}

// ---------------- fused GEMM + scan kernel ----------------
__global__ void __launch_bounds__(512, 2)
fused_gemm_scan(const float* __restrict__ x, const float* __restrict__ w_a)
{
    __shared__ __align__(16) char smem[sizeof(GemmSmem)];
    if (blockIdx.x < GEMM_BLOCKS) gemm_part(x, w_a, smem);
    else                          scan_part(smem);
}

// ---------------- sparse decode: out[tb] = b_d + sum_i y_i * w_dT[c_i] ----------
__global__ void __launch_bounds__(256) decode_kernel(const float* __restrict__ b_d,
                                                     float* __restrict__ out)
{
    const int tb  = blockIdx.x;
    const int tid = threadIdx.x;

    __shared__ int   s_c[K_TOP];
    __shared__ float s_y[K_TOP];
    if (tid < K_TOP) {
        s_c[tid] = g_ycidx[(size_t)tb * K_TOP + tid];
        s_y[tid] = g_ycval[(size_t)tb * K_TOP + tid];
    }
    __syncthreads();

    float4 acc = *reinterpret_cast<const float4*>(&b_d[tid * 4]);
#pragma unroll
    for (int i = 0; i < K_TOP; i++) {
        float y = s_y[i];
        const float4 w = *reinterpret_cast<const float4*>(
            &g_wdt[(size_t)s_c[i] * D_OUT + tid * 4]);
        acc.x = fmaf(y, w.x, acc.x);
        acc.y = fmaf(y, w.y, acc.y);
        acc.z = fmaf(y, w.z, acc.z);
        acc.w = fmaf(y, w.w, acc.w);
    }
    *reinterpret_cast<float4*>(&out[(size_t)tb * D_OUT + tid * 4]) = acc;
}

// ---------------- host launch ----------------
extern "C" void kernel_launch(void* const* d_in, const int* in_sizes, int n_in,
                              void* d_out, int out_size)
{
    const float* x   = (const float*)d_in[0];   // [T, B, D_IN]
    const float* w_a = (const float*)d_in[1];   // [M, D_IN]
    const float* w_b = (const float*)d_in[2];   // [TC, TC]
    const float* w_d = (const float*)d_in[3];   // [D_OUT, M]
    const float* b_d = (const float*)d_in[4];   // [D_OUT]
    float* out = (float*)d_out;                 // [T, B, D_OUT]

    float *wbt, *wdt;
    cudaGetSymbolAddress((void**)&wbt, g_wbt);
    cudaGetSymbolAddress((void**)&wdt, g_wdt);

    // reset readiness counters (every replay)
    zero_cnt_kernel<<<1, 64>>>();

    // transpose w_b (4000x4000) and w_d (1024x1000)
    transpose_kernel<<<dim3(TC / 32, TC / 32), dim3(32, 8)>>>(w_b, wbt, TC, TC);
    transpose_kernel<<<dim3((M_COLS + 31) / 32, D_OUT / 32), dim3(32, 8)>>>(
        w_d, wdt, D_OUT, M_COLS);

    // fused: 512 GEMM tile blocks (producing za per-timestep) + 128 scan blocks
    fused_gemm_scan<<<GEMM_BLOCKS + B_SZ, 512>>>(x, w_a);

    // sparse decode for all timesteps
    decode_kernel<<<T_STEPS * B_SZ, 256>>>(b_d, out);
}

// round 9
// speedup vs baseline: 93.0577x; 1.1740x over previous
#include <cuda_runtime.h>
#include <math.h>

// ---------------- problem constants ----------------
#define T_STEPS 64
#define B_SZ    128
#define M_COLS  1000
#define N_CELLS 4
#define TC      4000      // M_COLS * N_CELLS
#define K_TOP   25
#define D_IN    1024
#define D_OUT   1024
#define GEMM_BLOCKS 512   // 64 timesteps x 8 column tiles

// ---------------- persistent device state ----------------
__device__ float g_za_all[T_STEPS * B_SZ * M_COLS]; // feedforward drive
__device__ float g_wbt  [TC * TC];                  // w_b transposed
__device__ float g_wdt  [M_COLS * D_OUT];           // w_d transposed
__device__ int   g_ycidx[T_STEPS * B_SZ * K_TOP];   // selected columns per (t,b)
__device__ float g_ycval[T_STEPS * B_SZ * K_TOP];   // max(y,0) per (t,b)
__device__ int   g_cnt  [T_STEPS];                  // za readiness counters

// ---------------- init (counters must reset every graph replay) ----------------
__global__ void zero_cnt_kernel() {
    if (threadIdx.x < T_STEPS) g_cnt[threadIdx.x] = 0;
}

// ---------------- generic 32x32 tiled transpose with bounds ----------------
__global__ void transpose_kernel(const float* __restrict__ in, float* __restrict__ out,
                                 int rows, int cols)
{
    __shared__ float tile[32][33];
    int c0 = blockIdx.x * 32, r0 = blockIdx.y * 32;
#pragma unroll
    for (int j = 0; j < 32; j += 8) {
        int r = r0 + threadIdx.y + j, c = c0 + threadIdx.x;
        if (r < rows && c < cols)
            tile[threadIdx.y + j][threadIdx.x] = in[(size_t)r * cols + c];
    }
    __syncthreads();
#pragma unroll
    for (int j = 0; j < 32; j += 8) {
        int c = c0 + threadIdx.y + j, r = r0 + threadIdx.x;
        if (r < rows && c < cols)
            out[(size_t)c * rows + r] = tile[threadIdx.x][threadIdx.y + j];
    }
}

// ---------------- helpers ----------------
__device__ __forceinline__ unsigned int ord_key(float f) {
    unsigned int u = __float_as_uint(f);
    return (u & 0x80000000u) ? ~u : (u | 0x80000000u);
}

__device__ __forceinline__ void tree_max32(const float v[32], float& bv, int& bj)
{
    float tv[16]; int tj[16];
#pragma unroll
    for (int j = 0; j < 16; j++) {
        bool t = v[2 * j + 1] > v[2 * j];
        tv[j] = t ? v[2 * j + 1] : v[2 * j];
        tj[j] = t ? 2 * j + 1 : 2 * j;
    }
#pragma unroll
    for (int s = 8; s >= 1; s >>= 1) {
#pragma unroll
        for (int j = 0; j < s; j++) {
            bool t = tv[j + s] > tv[j];
            tv[j] = t ? tv[j + s] : tv[j];
            tj[j] = t ? tj[j + s] : tj[j];
        }
    }
    bv = tv[0]; bj = tj[0];
}

// ---------------- shared memory overlays ----------------
struct GemmSmem {                       // 34,304 B
    float As[2][16][128 + 4];
    float Bs[2][16][128 + 8];
};
struct ScanSmem {                       // ~25.3 KB
    float         psi[TC];
    float         lam[M_COLS];
    float         sig[M_COLS];
    unsigned char win[M_COLS];
    int           didx [K_TOP];
    float         delta[K_TOP];
};

// ---------------- GEMM part: one 128x128 za tile, then signal ----------------
__device__ void gemm_part(const float* __restrict__ x, const float* __restrict__ w_a,
                          char* smem, int gbid)
{
    GemmSmem* S = reinterpret_cast<GemmSmem*>(smem);
    const int t   = gbid >> 3;
    const int n0  = (gbid & 7) * 128;
    const int tid = threadIdx.x;
    const int tn  = tid & 31;          // column group (tn*4)
    const int tm  = tid >> 5;          // row group (tm*8)
    const int arow = tid >> 2, aq = tid & 3;

    const float* A = x + (size_t)t * B_SZ * D_IN;      // [128,1024]
    float*       C = g_za_all + (size_t)t * B_SZ * M_COLS;

    unsigned long long acc[8][2];
#pragma unroll
    for (int i = 0; i < 8; i++) { acc[i][0] = 0ull; acc[i][1] = 0ull; }

    float4 aR = *reinterpret_cast<const float4*>(&A[(size_t)arow * D_IN + aq * 4]);
    float4 bR = make_float4(0.f, 0.f, 0.f, 0.f);
    if (n0 + arow < M_COLS)
        bR = *reinterpret_cast<const float4*>(&w_a[(size_t)(n0 + arow) * D_IN + aq * 4]);
    {
        S->As[0][aq * 4 + 0][arow] = aR.x; S->As[0][aq * 4 + 1][arow] = aR.y;
        S->As[0][aq * 4 + 2][arow] = aR.z; S->As[0][aq * 4 + 3][arow] = aR.w;
        S->Bs[0][aq * 4 + 0][arow] = bR.x; S->Bs[0][aq * 4 + 1][arow] = bR.y;
        S->Bs[0][aq * 4 + 2][arow] = bR.z; S->Bs[0][aq * 4 + 3][arow] = bR.w;
    }
    __syncthreads();

    const int nk = D_IN / 16;                          // 64
    for (int kt = 0; kt < nk; kt++) {
        const int buf = kt & 1;
        if (kt + 1 < nk) {
            int kb = (kt + 1) * 16;
            aR = *reinterpret_cast<const float4*>(&A[(size_t)arow * D_IN + kb + aq * 4]);
            bR = make_float4(0.f, 0.f, 0.f, 0.f);
            if (n0 + arow < M_COLS)
                bR = *reinterpret_cast<const float4*>(&w_a[(size_t)(n0 + arow) * D_IN + kb + aq * 4]);
        }
#pragma unroll
        for (int k = 0; k < 16; k++) {
            float4 a0 = *reinterpret_cast<const float4*>(&S->As[buf][k][tm * 8]);
            float4 a1 = *reinterpret_cast<const float4*>(&S->As[buf][k][tm * 8 + 4]);
            const unsigned long long* bp =
                reinterpret_cast<const unsigned long long*>(&S->Bs[buf][k][tn * 4]);
            unsigned long long b2[2] = {bp[0], bp[1]};
            float av[8] = {a0.x, a0.y, a0.z, a0.w, a1.x, a1.y, a1.z, a1.w};
#pragma unroll
            for (int i = 0; i < 8; i++) {
                unsigned int au = __float_as_uint(av[i]);
                unsigned long long ap;
                asm("mov.b64 %0, {%1, %1};" : "=l"(ap) : "r"(au));
                asm("fma.rn.f32x2 %0, %1, %2, %0;" : "+l"(acc[i][0]) : "l"(ap), "l"(b2[0]));
                asm("fma.rn.f32x2 %0, %1, %2, %0;" : "+l"(acc[i][1]) : "l"(ap), "l"(b2[1]));
            }
        }
        if (kt + 1 < nk) {
            const int nb = buf ^ 1;
            S->As[nb][aq * 4 + 0][arow] = aR.x; S->As[nb][aq * 4 + 1][arow] = aR.y;
            S->As[nb][aq * 4 + 2][arow] = aR.z; S->As[nb][aq * 4 + 3][arow] = aR.w;
            S->Bs[nb][aq * 4 + 0][arow] = bR.x; S->Bs[nb][aq * 4 + 1][arow] = bR.y;
            S->Bs[nb][aq * 4 + 2][arow] = bR.z; S->Bs[nb][aq * 4 + 3][arow] = bR.w;
            __syncthreads();
        }
    }

#pragma unroll
    for (int i = 0; i < 8; i++) {
        int gm = tm * 8 + i;
#pragma unroll
        for (int j = 0; j < 2; j++) {
            unsigned int lo, hi;
            asm("mov.b64 {%0, %1}, %2;" : "=r"(lo), "=r"(hi) : "l"(acc[i][j]));
            int gn = n0 + tn * 4 + 2 * j;
            if (gn < M_COLS)     C[(size_t)gm * M_COLS + gn]     = __uint_as_float(lo);
            if (gn + 1 < M_COLS) C[(size_t)gm * M_COLS + gn + 1] = __uint_as_float(hi);
        }
    }

    // signal: tile ready
    __threadfence();
    __syncthreads();
    if (threadIdx.x == 0) atomicAdd(&g_cnt[t], 1);
}

// ---------------- scan part: one block per batch row, z_b in registers ----------
__device__ void scan_part(char* smem, int b)
{
    ScanSmem* S = reinterpret_cast<ScanSmem*>(smem);
    const int tid    = threadIdx.x;
    const int lane   = tid & 31;
    const int warpid = tid >> 5;

    const int c0 = tid;                // column 0..511
    const int c1 = tid + 512;          // column 512..1023 (valid < 1000)
    const bool two = (c1 < M_COLS);

    for (int i = tid; i < TC; i += 512) S->psi[i] = 0.f;
    float4 z0 = make_float4(0.f, 0.f, 0.f, 0.f);
    float4 z1 = make_float4(0.f, 0.f, 0.f, 0.f);
    __syncthreads();

    for (int t = 0; t < T_STEPS; t++) {
        // wait for za[t] (8 tiles)
        if (tid == 0) {
            unsigned int v;
            do {
                asm volatile("ld.acquire.gpu.u32 %0, [%1];"
                             : "=r"(v) : "l"(&g_cnt[t]) : "memory");
            } while (v < 8u);
        }
        __syncthreads();

        // ---- fused: rank-25 z_b update (t>0) + winner/lam + psi decay ----
        if (t > 0) {
            float4 a0 = make_float4(0.5f * z0.x, 0.5f * z0.y, 0.5f * z0.z, 0.5f * z0.w);
            float4 a1 = make_float4(0.5f * z1.x, 0.5f * z1.y, 0.5f * z1.z, 0.5f * z1.w);
#pragma unroll
            for (int i = 0; i < K_TOP; i++) {
                float d = S->delta[i];
                const float* base = &g_wbt[(size_t)S->didx[i] * TC];
                float4 w0 = *reinterpret_cast<const float4*>(&base[c0 * 4]);
                a0.x = fmaf(d, w0.x, a0.x); a0.y = fmaf(d, w0.y, a0.y);
                a0.z = fmaf(d, w0.z, a0.z); a0.w = fmaf(d, w0.w, a0.w);
                if (two) {
                    float4 w1 = *reinterpret_cast<const float4*>(&base[c1 * 4]);
                    a1.x = fmaf(d, w1.x, a1.x); a1.y = fmaf(d, w1.y, a1.y);
                    a1.z = fmaf(d, w1.z, a1.z); a1.w = fmaf(d, w1.w, a1.w);
                }
            }
            z0 = a0; z1 = a1;
        }

        const float* zab = g_za_all + ((size_t)t * B_SZ + b) * M_COLS;
#pragma unroll
        for (int h = 0; h < 2; h++) {
            int c = (h == 0) ? c0 : c1;
            if (h == 1 && !two) break;
            float4 z = (h == 0) ? z0 : z1;
            float  zac = __ldcg(&zab[c]);
            float4 ph  = *reinterpret_cast<const float4*>(&S->psi[c * 4]);
            float sig[4] = {zac + z.x, zac + z.y, zac + z.z, zac + z.w};
            float pv [4] = {sig[0] * (1.f - ph.x), sig[1] * (1.f - ph.y),
                            sig[2] * (1.f - ph.z), sig[3] * (1.f - ph.w)};
            float best = pv[0]; int bw = 0;
#pragma unroll
            for (int n = 1; n < N_CELLS; n++)
                if (pv[n] > best) { best = pv[n]; bw = n; }
            S->lam[c] = best;
            S->win[c] = (unsigned char)bw;
            S->sig[c] = sig[bw];
            *reinterpret_cast<float4*>(&S->psi[c * 4]) =
                make_float4(0.5f * ph.x, 0.5f * ph.y, 0.5f * ph.z, 0.5f * ph.w);
        }
        __syncthreads();

        // ---- top-K by warp 0 via REDUX (value desc, col asc on ties) ----
        if (warpid == 0) {
            float v[32];
#pragma unroll
            for (int j = 0; j < 32; j++) {
                int c = j * 32 + lane;
                v[j] = (c < M_COLS) ? S->lam[c] : -INFINITY;
            }
            float lv; int lj;
            tree_max32(v, lv, lj);
            int mycol = 0;

            for (int it = 0; it < K_TOP; it++) {
                unsigned int key = ord_key(lv);
                unsigned int m   = __reduce_max_sync(0xffffffffu, key);
                unsigned int cand = (key == m) ? (unsigned int)(lj * 32 + lane)
                                               : 0xffffffffu;
                unsigned int c = __reduce_min_sync(0xffffffffu, cand);
                if (lane == it) mycol = (int)c;
                if (((int)c & 31) == lane) {
                    v[(int)c >> 5] = -INFINITY;
                    tree_max32(v, lv, lj);
                }
            }
            __syncwarp();

            if (lane < K_TOP) {
                int   c    = mycol;
                int   w    = (int)S->win[c];
                int   cell = c * N_CELLS + w;
                float y    = tanhf(S->sig[c]);
                float pd   = S->psi[cell];
                S->didx [lane] = cell;
                S->delta[lane] = fmaxf(y - pd, 0.f);
                S->psi[cell]   = fmaxf(pd, y);
                size_t o = ((size_t)t * B_SZ + b) * K_TOP + lane;
                g_ycidx[o] = c;
                g_ycval[o] = fmaxf(y, 0.f);
            }
        }
        __syncthreads();
    }
}

// ---------------- fused GEMM + scan kernel (scan blocks FIRST) ----------------
__global__ void __launch_bounds__(512, 2)
fused_gemm_scan(const float* __restrict__ x, const float* __restrict__ w_a)
{
    __shared__ __align__(16) char smem[sizeof(GemmSmem)];
    if (blockIdx.x < B_SZ) scan_part(smem, blockIdx.x);
    else                   gemm_part(x, w_a, smem, blockIdx.x - B_SZ);
}

// ---------------- sparse decode: out[tb] = b_d + sum_i y_i * w_dT[c_i] ----------
__global__ void __launch_bounds__(256) decode_kernel(const float* __restrict__ b_d,
                                                     float* __restrict__ out)
{
    const int tb  = blockIdx.x;
    const int tid = threadIdx.x;

    __shared__ int   s_c[K_TOP];
    __shared__ float s_y[K_TOP];
    if (tid < K_TOP) {
        s_c[tid] = g_ycidx[(size_t)tb * K_TOP + tid];
        s_y[tid] = g_ycval[(size_t)tb * K_TOP + tid];
    }
    __syncthreads();

    float4 acc = *reinterpret_cast<const float4*>(&b_d[tid * 4]);
#pragma unroll
    for (int i = 0; i < K_TOP; i++) {
        float y = s_y[i];
        const float4 w = *reinterpret_cast<const float4*>(
            &g_wdt[(size_t)s_c[i] * D_OUT + tid * 4]);
        acc.x = fmaf(y, w.x, acc.x);
        acc.y = fmaf(y, w.y, acc.y);
        acc.z = fmaf(y, w.z, acc.z);
        acc.w = fmaf(y, w.w, acc.w);
    }
    *reinterpret_cast<float4*>(&out[(size_t)tb * D_OUT + tid * 4]) = acc;
}

// ---------------- host launch ----------------
extern "C" void kernel_launch(void* const* d_in, const int* in_sizes, int n_in,
                              void* d_out, int out_size)
{
    const float* x   = (const float*)d_in[0];   // [T, B, D_IN]
    const float* w_a = (const float*)d_in[1];   // [M, D_IN]
    const float* w_b = (const float*)d_in[2];   // [TC, TC]
    const float* w_d = (const float*)d_in[3];   // [D_OUT, M]
    const float* b_d = (const float*)d_in[4];   // [D_OUT]
    float* out = (float*)d_out;                 // [T, B, D_OUT]

    float *wbt, *wdt;
    cudaGetSymbolAddress((void**)&wbt, g_wbt);
    cudaGetSymbolAddress((void**)&wdt, g_wdt);

    // reset readiness counters (every replay)
    zero_cnt_kernel<<<1, 64>>>();

    // transpose w_b (4000x4000) and w_d (1024x1000)
    transpose_kernel<<<dim3(TC / 32, TC / 32), dim3(32, 8)>>>(w_b, wbt, TC, TC);
    transpose_kernel<<<dim3((M_COLS + 31) / 32, D_OUT / 32), dim3(32, 8)>>>(
        w_d, wdt, D_OUT, M_COLS);

    // fused: 128 scan blocks (dispatched first) + 512 GEMM tile blocks
    fused_gemm_scan<<<B_SZ + GEMM_BLOCKS, 512>>>(x, w_a);

    // sparse decode for all timesteps
    decode_kernel<<<T_STEPS * B_SZ, 256>>>(b_d, out);
}